// round 5
// baseline (speedup 1.0000x reference)
#include <cuda_runtime.h>
#include <math.h>
#include <stdint.h>

#define S_ 32
#define T_ 32
#define B_ 512
#define H_ 1024
#define E_ 256
#define A_ 1024
#define VS_ 64
#define VT_ 70
#define G3H (3*H_)
#define START_TOK 1

// ---------------- device scratch (static, no runtime allocation) ----------------
__device__ float g_token_gi_enc[VS_ * G3H];            // emb_src @ W_ih_enc^T + b_ih_enc
__device__ float g_token_gi_dec[VT_ * G3H];            // emb_tgt @ W_ih_dec[:,H:]^T + b_ih_dec
__device__ float g_h[B_ * H_];                         // current hidden
__device__ float g_gates[B_ * G3H];                    // h @ W_hh^T + b_hh
__device__ float g_gi[B_ * G3H];                       // ctx @ W_ih_dec[:,:H]^T
__device__ float g_enc_ops[(size_t)S_ * B_ * H_];      // encoder outputs (S,B,H)
__device__ float g_encW[(size_t)S_ * B_ * A_];         // enc_ops @ W_attn[H:,:] + b_attn
__device__ float g_hW[B_ * A_];                        // h @ W_attn[:H,:]
__device__ float g_scores[S_ * B_];
__device__ float g_alpha[S_ * B_];
__device__ float g_ctx[B_ * H_];
__device__ int   g_x[B_];

// ---------------- generic fp32 tiled GEMM ----------------
// C[M,N] = A[M,K] @ B + bias
//   BNK=1 : B is weights W[N,K] row-major (C[m,n] = sum_k A[m,k]*W[n,k])
//   BNK=0 : B is [K,N] row-major          (C[m,n] = sum_k A[m,k]*B[k,n])
// K % 32 == 0, N % 64 == 0 required; M guarded.
template <int BNK>
__global__ __launch_bounds__(256) void gemm_k(
    const float* __restrict__ Ap, const float* __restrict__ Bp,
    const float* __restrict__ bias, float* __restrict__ Cp,
    int M, int N, int K, int lda, int ldb, int ldc)
{
    __shared__ float As[32][65];
    __shared__ float Bs[32][65];
    const int tid = threadIdx.x;
    const int tx = tid & 15, ty = tid >> 4;
    const int m0 = blockIdx.y * 64, n0 = blockIdx.x * 64;

    float acc[4][4];
#pragma unroll
    for (int i = 0; i < 4; ++i)
#pragma unroll
        for (int j = 0; j < 4; ++j) acc[i][j] = 0.f;

    for (int kt = 0; kt < K; kt += 32) {
        // ---- load A tile (64 rows x 32 k), store k-major into shared ----
        {
            int r = tid >> 3, c = tid & 7;
#pragma unroll
            for (int p = 0; p < 2; ++p) {
                int row = r + p * 32;
                int m = m0 + row;
                float4 v = make_float4(0.f, 0.f, 0.f, 0.f);
                if (m < M)
                    v = *reinterpret_cast<const float4*>(Ap + (size_t)m * lda + kt + c * 4);
                As[c * 4 + 0][row] = v.x; As[c * 4 + 1][row] = v.y;
                As[c * 4 + 2][row] = v.z; As[c * 4 + 3][row] = v.w;
            }
        }
        // ---- load B tile ----
        if (BNK) {
            int r = tid >> 3, c = tid & 7;
#pragma unroll
            for (int p = 0; p < 2; ++p) {
                int row = r + p * 32;
                float4 v = *reinterpret_cast<const float4*>(Bp + (size_t)(n0 + row) * ldb + kt + c * 4);
                Bs[c * 4 + 0][row] = v.x; Bs[c * 4 + 1][row] = v.y;
                Bs[c * 4 + 2][row] = v.z; Bs[c * 4 + 3][row] = v.w;
            }
        } else {
            int r = tid >> 4, c = tid & 15;
#pragma unroll
            for (int p = 0; p < 2; ++p) {
                int kk = r + p * 16;
                float4 v = *reinterpret_cast<const float4*>(Bp + (size_t)(kt + kk) * ldb + n0 + c * 4);
                Bs[kk][c * 4 + 0] = v.x; Bs[kk][c * 4 + 1] = v.y;
                Bs[kk][c * 4 + 2] = v.z; Bs[kk][c * 4 + 3] = v.w;
            }
        }
        __syncthreads();

#pragma unroll
        for (int kk = 0; kk < 32; ++kk) {
            float a0 = As[kk][ty * 4 + 0], a1 = As[kk][ty * 4 + 1];
            float a2 = As[kk][ty * 4 + 2], a3 = As[kk][ty * 4 + 3];
            float b0 = Bs[kk][tx * 4 + 0], b1 = Bs[kk][tx * 4 + 1];
            float b2 = Bs[kk][tx * 4 + 2], b3 = Bs[kk][tx * 4 + 3];
            acc[0][0] += a0 * b0; acc[0][1] += a0 * b1; acc[0][2] += a0 * b2; acc[0][3] += a0 * b3;
            acc[1][0] += a1 * b0; acc[1][1] += a1 * b1; acc[1][2] += a1 * b2; acc[1][3] += a1 * b3;
            acc[2][0] += a2 * b0; acc[2][1] += a2 * b1; acc[2][2] += a2 * b2; acc[2][3] += a2 * b3;
            acc[3][0] += a3 * b0; acc[3][1] += a3 * b1; acc[3][2] += a3 * b2; acc[3][3] += a3 * b3;
        }
        __syncthreads();
    }

#pragma unroll
    for (int i = 0; i < 4; ++i) {
        int m = m0 + ty * 4 + i;
        if (m < M) {
#pragma unroll
            for (int j = 0; j < 4; ++j) {
                int n = n0 + tx * 4 + j;
                float v = acc[i][j];
                if (bias) v += bias[n];
                Cp[(size_t)m * ldc + n] = v;
            }
        }
    }
}

// ---------------- misc kernels ----------------
__global__ void init_kernel(const int* __restrict__ target, float* __restrict__ out)
{
    int idx = blockIdx.x * blockDim.x + threadIdx.x;   // covers B*H
    if (idx < B_ * H_) g_h[idx] = 0.f;
    if (idx < B_) g_x[idx] = target[idx];              // target[0, b]
    if (idx < B_ * VT_) {
        int v = idx % VT_;
        out[idx] = (v == START_TOK) ? 1.f : 0.f;       // outputs[0] one-hot
    }
}

__global__ void enc_pointwise(const int* __restrict__ source, int s)
{
    int idx = blockIdx.x * blockDim.x + threadIdx.x;
    int b = idx >> 10, k = idx & 1023;
    int tok = source[s * B_ + b];
    const float* tg = g_token_gi_enc + tok * G3H;
    const float* gh = g_gates + b * G3H;
    float ir = tg[k], iz = tg[H_ + k], in_ = tg[2 * H_ + k];
    float hr = gh[k], hz = gh[H_ + k], hn = gh[2 * H_ + k];
    float r = 1.f / (1.f + expf(-(ir + hr)));
    float z = 1.f / (1.f + expf(-(iz + hz)));
    float n = tanhf(in_ + r * hn);
    float hprev = g_h[idx];
    float hnew = (1.f - z) * n + z * hprev;
    g_h[idx] = hnew;
    g_enc_ops[((size_t)s * B_ + b) * H_ + k] = hnew;
}

__global__ void dec_pointwise()
{
    int idx = blockIdx.x * blockDim.x + threadIdx.x;
    int b = idx >> 10, k = idx & 1023;
    int tok = g_x[b];
    const float* tg = g_token_gi_dec + tok * G3H;
    const float* gi = g_gi + b * G3H;
    const float* gh = g_gates + b * G3H;
    float ir = tg[k] + gi[k];
    float iz = tg[H_ + k] + gi[H_ + k];
    float in_ = tg[2 * H_ + k] + gi[2 * H_ + k];
    float hr = gh[k], hz = gh[H_ + k], hn = gh[2 * H_ + k];
    float r = 1.f / (1.f + expf(-(ir + hr)));
    float z = 1.f / (1.f + expf(-(iz + hz)));
    float n = tanhf(in_ + r * hn);
    float hprev = g_h[idx];
    g_h[idx] = (1.f - z) * n + z * hprev;
}

// one warp per (s,b): score = sum_a v[a]*tanh(encW[s,b,a] + hW[b,a])
__global__ void scores_kernel(const float* __restrict__ v_attn)
{
    int gid = blockIdx.x * blockDim.x + threadIdx.x;
    int warp = gid >> 5, lane = gid & 31;
    int b = warp & (B_ - 1);
    const float* e = g_encW + (size_t)warp * A_;
    const float* hw = g_hW + (size_t)b * A_;
    float acc = 0.f;
#pragma unroll 4
    for (int a = lane; a < A_; a += 32)
        acc += v_attn[a] * tanhf(e[a] + hw[a]);
#pragma unroll
    for (int off = 16; off; off >>= 1)
        acc += __shfl_xor_sync(0xffffffffu, acc, off);
    if (!lane) g_scores[warp] = acc;
}

// per-b softmax over S=32 source positions; also writes attn output row
__global__ void softmax_kernel(float* __restrict__ out_attn, int t)
{
    int b = blockIdx.x * blockDim.x + threadIdx.x;
    if (b >= B_) return;
    float vals[S_];
    float m = -1e30f;
#pragma unroll
    for (int s = 0; s < S_; ++s) { vals[s] = g_scores[s * B_ + b]; m = fmaxf(m, vals[s]); }
    float sum = 0.f;
#pragma unroll
    for (int s = 0; s < S_; ++s) { vals[s] = expf(vals[s] - m); sum += vals[s]; }
    float inv = 1.f / sum;
    float* ao = out_attn + (size_t)(t - 1) * B_ * S_ + (size_t)b * S_;
#pragma unroll
    for (int s = 0; s < S_; ++s) {
        float a = vals[s] * inv;
        g_alpha[s * B_ + b] = a;
        ao[s] = a;
    }
}

__global__ void ctx_kernel()
{
    int idx = blockIdx.x * blockDim.x + threadIdx.x;
    int b = idx >> 10, h = idx & 1023;
    float acc = 0.f;
#pragma unroll
    for (int s = 0; s < S_; ++s)
        acc += g_alpha[s * B_ + b] * g_enc_ops[((size_t)s * B_ + b) * H_ + h];
    g_ctx[idx] = acc;
}

// logits = h @ W_out + b_out ; write output row t ; pick next input token
__global__ __launch_bounds__(256) void logits_kernel(
    const float* __restrict__ W_out, const float* __restrict__ b_out,
    const int* __restrict__ target, const int* __restrict__ tf_flag,
    int t, float* __restrict__ out)
{
    __shared__ float sh[H_];
    __shared__ float sl[VT_];
    int b = blockIdx.x, tid = threadIdx.x;
    for (int i = tid; i < H_; i += 256) sh[i] = g_h[b * H_ + i];
    __syncthreads();
    if (tid < VT_) {
        float acc = b_out[tid];
        for (int k = 0; k < H_; ++k) acc += sh[k] * W_out[k * VT_ + tid];
        sl[tid] = acc;
        out[((size_t)t * B_ + b) * VT_ + tid] = acc;
    }
    __syncthreads();
    if (tid == 0) {
        int x;
        if (*tf_flag) {
            x = target[t * B_ + b];
        } else {
            int best = 0; float bv = sl[0];
            for (int v = 1; v < VT_; ++v)
                if (sl[v] > bv) { bv = sl[v]; best = v; }
            x = best;
        }
        g_x[b] = x;
    }
}

// ---------------- orchestration ----------------
extern "C" void kernel_launch(void* const* d_in, const int* in_sizes, int n_in,
                              void* d_out, int out_size)
{
    const int*   source   = (const int*)  d_in[0];
    const int*   target   = (const int*)  d_in[1];
    const int*   tf       = (const int*)  d_in[2];
    const float* emb_src  = (const float*)d_in[3];
    const float* W_ih_enc = (const float*)d_in[4];
    const float* W_hh_enc = (const float*)d_in[5];
    const float* b_ih_enc = (const float*)d_in[6];
    const float* b_hh_enc = (const float*)d_in[7];
    const float* emb_tgt  = (const float*)d_in[8];
    const float* W_attn   = (const float*)d_in[9];
    const float* b_attn   = (const float*)d_in[10];
    const float* v_attn   = (const float*)d_in[11];
    const float* W_ih_dec = (const float*)d_in[12];
    const float* W_hh_dec = (const float*)d_in[13];
    const float* b_ih_dec = (const float*)d_in[14];
    const float* b_hh_dec = (const float*)d_in[15];
    const float* W_out    = (const float*)d_in[16];
    const float* b_out    = (const float*)d_in[17];

    float* out = (float*)d_out;
    float* out_attn = out + (size_t)T_ * B_ * VT_;

    float *p_tge, *p_tgd, *p_h, *p_gates, *p_gi, *p_enc, *p_encW, *p_hW, *p_ctx;
    cudaGetSymbolAddress((void**)&p_tge,  g_token_gi_enc);
    cudaGetSymbolAddress((void**)&p_tgd,  g_token_gi_dec);
    cudaGetSymbolAddress((void**)&p_h,    g_h);
    cudaGetSymbolAddress((void**)&p_gates,g_gates);
    cudaGetSymbolAddress((void**)&p_gi,   g_gi);
    cudaGetSymbolAddress((void**)&p_enc,  g_enc_ops);
    cudaGetSymbolAddress((void**)&p_encW, g_encW);
    cudaGetSymbolAddress((void**)&p_hW,   g_hW);
    cudaGetSymbolAddress((void**)&p_ctx,  g_ctx);

    const int PW_BLOCKS = (B_ * H_) / 256;   // 2048

    // init: zero hidden, x0 = target[0], outputs[0] one-hot
    init_kernel<<<PW_BLOCKS, 256>>>(target, out);

    // token input-gate tables (replace embedding + input GEMM with a lookup)
    gemm_k<1><<<dim3(G3H / 64, (VS_ + 63) / 64), 256>>>(
        emb_src, W_ih_enc, b_ih_enc, p_tge, VS_, G3H, E_, E_, E_, G3H);
    // FIX: lda for emb_tgt is E_ (row stride of the (VT,E) embedding table),
    // NOT H_+E_. ldb stays H_+E_ (row stride of W_ih_dec).
    gemm_k<1><<<dim3(G3H / 64, (VT_ + 63) / 64), 256>>>(
        emb_tgt, W_ih_dec + H_, b_ih_dec, p_tgd, VT_, G3H, E_, E_, H_ + E_, G3H);

    // -------- encoder --------
    for (int s = 0; s < S_; ++s) {
        gemm_k<1><<<dim3(G3H / 64, B_ / 64), 256>>>(
            p_h, W_hh_enc, b_hh_enc, p_gates, B_, G3H, H_, H_, H_, G3H);
        enc_pointwise<<<PW_BLOCKS, 256>>>(source, s);
    }

    // attention precompute: enc_ops @ W_attn[H:,:] + b_attn  (invariant over decoder steps)
    gemm_k<0><<<dim3(A_ / 64, (S_ * B_) / 64), 256>>>(
        p_enc, W_attn + (size_t)H_ * A_, b_attn, p_encW, S_ * B_, A_, H_, H_, A_, A_);

    // -------- decoder --------
    for (int t = 1; t < T_; ++t) {
        gemm_k<0><<<dim3(A_ / 64, B_ / 64), 256>>>(
            p_h, W_attn, nullptr, p_hW, B_, A_, H_, H_, A_, A_);
        scores_kernel<<<(S_ * B_ * 32) / 256, 256>>>(v_attn);
        softmax_kernel<<<2, 256>>>(out_attn, t);
        ctx_kernel<<<PW_BLOCKS, 256>>>();
        gemm_k<1><<<dim3(G3H / 64, B_ / 64), 256>>>(
            p_ctx, W_ih_dec, nullptr, p_gi, B_, G3H, H_, H_, H_ + E_, G3H);
        gemm_k<1><<<dim3(G3H / 64, B_ / 64), 256>>>(
            p_h, W_hh_dec, b_hh_dec, p_gates, B_, G3H, H_, H_, H_, G3H);
        dec_pointwise<<<PW_BLOCKS, 256>>>();
        logits_kernel<<<B_, 256>>>(W_out, b_out, target, tf, t, out);
    }
}

// round 8
// speedup vs baseline: 1.8644x; 1.8644x over previous
#include <cuda_runtime.h>
#include <cuda_bf16.h>
#include <math.h>
#include <stdint.h>

#define S_ 32
#define T_ 32
#define B_ 512
#define H_ 1024
#define E_ 256
#define A_ 1024
#define VS_ 64
#define VT_ 70
#define G3H (3*H_)
#define START_TOK 1

// ---------------- device scratch (static, no runtime allocation) ----------------
__device__ float g_token_gi_enc[VS_ * G3H];
__device__ float g_token_gi_dec[VT_ * G3H];
__device__ float g_h[B_ * H_];
__device__ float g_gates[B_ * G3H];
__device__ float g_gi[B_ * G3H];
__device__ float g_enc_ops[(size_t)S_ * B_ * H_];
__device__ float g_encW[(size_t)S_ * B_ * A_];
__device__ float g_hW[B_ * A_];
__device__ float g_scores[S_ * B_];
__device__ float g_alpha[S_ * B_];
__device__ int   g_x[B_];

// bf16 split activations
__device__ __nv_bfloat16 g_h_hi[B_ * H_],  g_h_lo[B_ * H_];
__device__ __nv_bfloat16 g_ctx_hi[B_ * H_], g_ctx_lo[B_ * H_];
__device__ __nv_bfloat16 g_enc_hi[(size_t)S_ * B_ * H_], g_enc_lo[(size_t)S_ * B_ * H_];
// bf16 split weights (K-major [N,K])
__device__ __nv_bfloat16 g_Whe_hi[G3H * H_], g_Whe_lo[G3H * H_];       // W_hh_enc
__device__ __nv_bfloat16 g_Whd_hi[G3H * H_], g_Whd_lo[G3H * H_];       // W_hh_dec
__device__ __nv_bfloat16 g_Wid_hi[G3H * H_], g_Wid_lo[G3H * H_];       // W_ih_dec[:, :H]
__device__ __nv_bfloat16 g_Wat_hi[A_ * 2 * H_], g_Wat_lo[A_ * 2 * H_]; // W_attn^T [A, 2H]

// ---------------- mma.sync helpers (arch-neutral: work on compute_103) ----------------
__device__ __forceinline__ uint32_t smem_u32(const void* p) {
    uint32_t a;
    asm("{ .reg .u64 t; cvta.to.shared.u64 t, %1; cvt.u32.u64 %0, t; }" : "=r"(a) : "l"(p));
    return a;
}

#define LDSM_X4(r0, r1, r2, r3, addr) \
    asm volatile("ldmatrix.sync.aligned.m8n8.x4.shared.b16 {%0,%1,%2,%3}, [%4];" \
        : "=r"(r0), "=r"(r1), "=r"(r2), "=r"(r3) : "r"(addr))

__device__ __forceinline__ void mma16816(float* d, const uint32_t* a, const uint32_t* b) {
    asm volatile("mma.sync.aligned.m16n8k16.row.col.f32.bf16.bf16.f32 "
        "{%0,%1,%2,%3}, {%4,%5,%6,%7}, {%8,%9}, {%0,%1,%2,%3};"
        : "+f"(d[0]), "+f"(d[1]), "+f"(d[2]), "+f"(d[3])
        : "r"(a[0]), "r"(a[1]), "r"(a[2]), "r"(a[3]), "r"(b[0]), "r"(b[1]));
}

// ---------------- split-bf16 tensor-core GEMM (HMMA path) ----------------
// C[M,N] = (Ahi+Alo)[M,K] @ (Bhi+Blo)[N,K]^T + bias  (fp32 out; drops lo*lo)
// Requires: M % 128 == 0, N % 128 == 0, K % 64 == 0.
// CTA: 128x128 tile, 256 threads = 8 warps in 4(m) x 2(n); warp tile 32x64.
#define PAD_ 72                      // bf16 row stride in smem (64 + 8)
#define TILE_ELEMS (128 * PAD_)      // 9216 bf16 = 18432 B
#define HM_SMEM (4 * TILE_ELEMS * 2) // Ahi, Alo, Bhi, Blo = 73728 B

__global__ __launch_bounds__(256, 1) void hmma_gemm(
    const __nv_bfloat16* __restrict__ Ahi, const __nv_bfloat16* __restrict__ Alo, int lda,
    const __nv_bfloat16* __restrict__ Bhi, const __nv_bfloat16* __restrict__ Blo, int ldb,
    const float* __restrict__ bias, float* __restrict__ Cp, int ldc, int K)
{
    extern __shared__ __nv_bfloat16 sm[];
    const uint32_t sbase = smem_u32(sm);
    const int tid = threadIdx.x, lane = tid & 31, wid = tid >> 5;
    const int wm = wid >> 1, wn = wid & 1;
    const int m0 = blockIdx.y * 128, n0 = blockIdx.x * 128;

    float acc[2][8][4];
#pragma unroll
    for (int i = 0; i < 2; ++i)
#pragma unroll
        for (int j = 0; j < 8; ++j)
#pragma unroll
            for (int q = 0; q < 4; ++q) acc[i][j][q] = 0.f;

    const __nv_bfloat16* gA0 = Ahi + (size_t)m0 * lda;
    const __nv_bfloat16* gA1 = Alo + (size_t)m0 * lda;
    const __nv_bfloat16* gB0 = Bhi + (size_t)n0 * ldb;
    const __nv_bfloat16* gB1 = Blo + (size_t)n0 * ldb;

    // per-thread ldmatrix base addresses
    // A (x4 -> one 16x16): row = lane&15, k half = (lane>>4)*8
    const uint32_t aoff = ((uint32_t)(wm * 32 + (lane & 15)) * PAD_ + (lane >> 4) * 8) * 2;
    // B (x4 -> two 8x16 n-blocks): row = (lane&7) + (lane&16 ? 8:0), k half = ((lane>>3)&1)*8
    const uint32_t boff = ((uint32_t)(wn * 64 + (lane & 7) + ((lane & 16) ? 8 : 0)) * PAD_
                          + ((lane >> 3) & 1) * 8) * 2;
    const uint32_t sAhi = sbase;
    const uint32_t sAlo = sbase + TILE_ELEMS * 2;
    const uint32_t sBhi = sbase + 2 * TILE_ELEMS * 2;
    const uint32_t sBlo = sbase + 3 * TILE_ELEMS * 2;

    const int nchunks = K >> 6;
    for (int c = 0; c < nchunks; ++c) {
        const int koff = c << 6;
        if (c) __syncthreads();            // previous chunk's compute done before overwrite
        // load 4 tiles: 128 rows x 64 bf16 each; 1024 x uint4 per tile; 4 per thread
#pragma unroll
        for (int i = 0; i < 4; ++i) {
            const int j = tid + i * 256;
            const int row = j >> 3, q = j & 7;
            const size_t ga = (size_t)row * lda + koff + q * 8;
            const size_t gb = (size_t)row * ldb + koff + q * 8;
            const uint32_t so = (uint32_t)(row * PAD_ + q * 8) * 2;
            uint4 v0 = *reinterpret_cast<const uint4*>(gA0 + ga);
            uint4 v1 = *reinterpret_cast<const uint4*>(gA1 + ga);
            uint4 v2 = *reinterpret_cast<const uint4*>(gB0 + gb);
            uint4 v3 = *reinterpret_cast<const uint4*>(gB1 + gb);
            *reinterpret_cast<uint4*>(reinterpret_cast<char*>(sm) + so) = v0;
            *reinterpret_cast<uint4*>(reinterpret_cast<char*>(sm) + TILE_ELEMS * 2 + so) = v1;
            *reinterpret_cast<uint4*>(reinterpret_cast<char*>(sm) + 2 * TILE_ELEMS * 2 + so) = v2;
            *reinterpret_cast<uint4*>(reinterpret_cast<char*>(sm) + 3 * TILE_ELEMS * 2 + so) = v3;
        }
        __syncthreads();

#pragma unroll
        for (int ks = 0; ks < 4; ++ks) {
            const uint32_t kso = (uint32_t)(ks * 16) * 2;
            uint32_t ah[2][4], al[2][4];
#pragma unroll
            for (int mb = 0; mb < 2; ++mb) {
                const uint32_t off = aoff + (uint32_t)(mb * 16 * PAD_) * 2 + kso;
                LDSM_X4(ah[mb][0], ah[mb][1], ah[mb][2], ah[mb][3], sAhi + off);
                LDSM_X4(al[mb][0], al[mb][1], al[mb][2], al[mb][3], sAlo + off);
            }
            uint32_t bh[8][2], bl[8][2];
#pragma unroll
            for (int p = 0; p < 4; ++p) {
                const uint32_t off = boff + (uint32_t)(p * 16 * PAD_) * 2 + kso;
                LDSM_X4(bh[2*p][0], bh[2*p][1], bh[2*p+1][0], bh[2*p+1][1], sBhi + off);
                LDSM_X4(bl[2*p][0], bl[2*p][1], bl[2*p+1][0], bl[2*p+1][1], sBlo + off);
            }
#pragma unroll
            for (int mb = 0; mb < 2; ++mb)
#pragma unroll
                for (int nb = 0; nb < 8; ++nb) {
                    mma16816(acc[mb][nb], ah[mb], bh[nb]);
                    mma16816(acc[mb][nb], al[mb], bh[nb]);
                    mma16816(acc[mb][nb], ah[mb], bl[nb]);
                }
        }
    }

    // epilogue: d0/d1 -> (row, col/col+1), d2/d3 -> (row+8, col/col+1)
    const int mrow = m0 + wm * 32 + (lane >> 2);
    const int ncol = n0 + wn * 64 + (lane & 3) * 2;
#pragma unroll
    for (int mb = 0; mb < 2; ++mb) {
        const int m = mrow + mb * 16;
#pragma unroll
        for (int nb = 0; nb < 8; ++nb) {
            const int n = ncol + nb * 8;
            float bx = 0.f, by = 0.f;
            if (bias) { bx = bias[n]; by = bias[n + 1]; }
            float* c0 = Cp + (size_t)m * ldc + n;
            float* c1 = Cp + (size_t)(m + 8) * ldc + n;
            c0[0] = acc[mb][nb][0] + bx; c0[1] = acc[mb][nb][1] + by;
            c1[0] = acc[mb][nb][2] + bx; c1[1] = acc[mb][nb][3] + by;
        }
    }
}

// ---------------- fp32 SIMT GEMM (tiny token tables only) ----------------
template <int BNK>
__global__ __launch_bounds__(256) void gemm_k(
    const float* __restrict__ Ap, const float* __restrict__ Bp,
    const float* __restrict__ bias, float* __restrict__ Cp,
    int M, int N, int K, int lda, int ldb, int ldc)
{
    __shared__ float As[32][65];
    __shared__ float Bs[32][65];
    const int tid = threadIdx.x;
    const int tx = tid & 15, ty = tid >> 4;
    const int m0 = blockIdx.y * 64, n0 = blockIdx.x * 64;
    float acc[4][4];
#pragma unroll
    for (int i = 0; i < 4; ++i)
#pragma unroll
        for (int j = 0; j < 4; ++j) acc[i][j] = 0.f;
    for (int kt = 0; kt < K; kt += 32) {
        {
            int r = tid >> 3, c = tid & 7;
#pragma unroll
            for (int p = 0; p < 2; ++p) {
                int row = r + p * 32;
                int m = m0 + row;
                float4 v = make_float4(0.f, 0.f, 0.f, 0.f);
                if (m < M)
                    v = *reinterpret_cast<const float4*>(Ap + (size_t)m * lda + kt + c * 4);
                As[c * 4 + 0][row] = v.x; As[c * 4 + 1][row] = v.y;
                As[c * 4 + 2][row] = v.z; As[c * 4 + 3][row] = v.w;
            }
        }
        {
            int r = tid >> 3, c = tid & 7;
#pragma unroll
            for (int p = 0; p < 2; ++p) {
                int row = r + p * 32;
                float4 v = *reinterpret_cast<const float4*>(Bp + (size_t)(n0 + row) * ldb + kt + c * 4);
                Bs[c * 4 + 0][row] = v.x; Bs[c * 4 + 1][row] = v.y;
                Bs[c * 4 + 2][row] = v.z; Bs[c * 4 + 3][row] = v.w;
            }
        }
        __syncthreads();
#pragma unroll
        for (int kk = 0; kk < 32; ++kk) {
            float a0 = As[kk][ty * 4 + 0], a1 = As[kk][ty * 4 + 1];
            float a2 = As[kk][ty * 4 + 2], a3 = As[kk][ty * 4 + 3];
            float b0 = Bs[kk][tx * 4 + 0], b1 = Bs[kk][tx * 4 + 1];
            float b2 = Bs[kk][tx * 4 + 2], b3 = Bs[kk][tx * 4 + 3];
            acc[0][0] += a0 * b0; acc[0][1] += a0 * b1; acc[0][2] += a0 * b2; acc[0][3] += a0 * b3;
            acc[1][0] += a1 * b0; acc[1][1] += a1 * b1; acc[1][2] += a1 * b2; acc[1][3] += a1 * b3;
            acc[2][0] += a2 * b0; acc[2][1] += a2 * b1; acc[2][2] += a2 * b2; acc[2][3] += a2 * b3;
            acc[3][0] += a3 * b0; acc[3][1] += a3 * b1; acc[3][2] += a3 * b2; acc[3][3] += a3 * b3;
        }
        __syncthreads();
    }
#pragma unroll
    for (int i = 0; i < 4; ++i) {
        int m = m0 + ty * 4 + i;
        if (m < M) {
#pragma unroll
            for (int j = 0; j < 4; ++j) {
                int n = n0 + tx * 4 + j;
                float v = acc[i][j];
                if (bias) v += bias[n];
                Cp[(size_t)m * ldc + n] = v;
            }
        }
    }
}

// ---------------- weight prep ----------------
__global__ void split_mat(const float* __restrict__ src, int ld, int cols,
                          __nv_bfloat16* __restrict__ hi, __nv_bfloat16* __restrict__ lo, int total)
{
    int idx = blockIdx.x * blockDim.x + threadIdx.x;
    if (idx >= total) return;
    int r = idx / cols, c = idx - r * cols;
    float x = src[(size_t)r * ld + c];
    __nv_bfloat16 h = __float2bfloat16(x);
    hi[idx] = h;
    lo[idx] = __float2bfloat16(x - __bfloat162float(h));
}

__global__ void transpose_split(const float* __restrict__ W,
                                __nv_bfloat16* __restrict__ hi, __nv_bfloat16* __restrict__ lo)
{
    int idx = blockIdx.x * blockDim.x + threadIdx.x;   // A_ * 2H
    if (idx >= A_ * 2 * H_) return;
    int n = idx >> 11, k = idx & 2047;
    float x = W[(size_t)k * A_ + n];
    __nv_bfloat16 h = __float2bfloat16(x);
    hi[idx] = h;
    lo[idx] = __float2bfloat16(x - __bfloat162float(h));
}

// ---------------- misc kernels ----------------
__global__ void init_kernel(const int* __restrict__ target, float* __restrict__ out)
{
    int idx = blockIdx.x * blockDim.x + threadIdx.x;
    if (idx < B_ * H_) {
        g_h[idx] = 0.f;
        g_h_hi[idx] = __float2bfloat16(0.f);
        g_h_lo[idx] = __float2bfloat16(0.f);
    }
    if (idx < B_) g_x[idx] = target[idx];
    if (idx < B_ * VT_) {
        int v = idx % VT_;
        out[idx] = (v == START_TOK) ? 1.f : 0.f;
    }
}

__global__ void enc_pointwise(const int* __restrict__ source, int s)
{
    int idx = blockIdx.x * blockDim.x + threadIdx.x;
    int b = idx >> 10, k = idx & 1023;
    int tok = source[s * B_ + b];
    const float* tg = g_token_gi_enc + tok * G3H;
    const float* gh = g_gates + b * G3H;
    float ir = tg[k], iz = tg[H_ + k], in_ = tg[2 * H_ + k];
    float hr = gh[k], hz = gh[H_ + k], hn = gh[2 * H_ + k];
    float r = 1.f / (1.f + expf(-(ir + hr)));
    float z = 1.f / (1.f + expf(-(iz + hz)));
    float n = tanhf(in_ + r * hn);
    float hprev = g_h[idx];
    float hnew = (1.f - z) * n + z * hprev;
    g_h[idx] = hnew;
    size_t eo = ((size_t)s * B_ + b) * H_ + k;
    g_enc_ops[eo] = hnew;
    __nv_bfloat16 hh = __float2bfloat16(hnew);
    __nv_bfloat16 hl = __float2bfloat16(hnew - __bfloat162float(hh));
    g_h_hi[idx] = hh; g_h_lo[idx] = hl;
    g_enc_hi[eo] = hh; g_enc_lo[eo] = hl;
}

__global__ void dec_pointwise()
{
    int idx = blockIdx.x * blockDim.x + threadIdx.x;
    int b = idx >> 10, k = idx & 1023;
    int tok = g_x[b];
    const float* tg = g_token_gi_dec + tok * G3H;
    const float* gi = g_gi + b * G3H;
    const float* gh = g_gates + b * G3H;
    float ir = tg[k] + gi[k];
    float iz = tg[H_ + k] + gi[H_ + k];
    float in_ = tg[2 * H_ + k] + gi[2 * H_ + k];
    float hr = gh[k], hz = gh[H_ + k], hn = gh[2 * H_ + k];
    float r = 1.f / (1.f + expf(-(ir + hr)));
    float z = 1.f / (1.f + expf(-(iz + hz)));
    float n = tanhf(in_ + r * hn);
    float hprev = g_h[idx];
    float hnew = (1.f - z) * n + z * hprev;
    g_h[idx] = hnew;
    __nv_bfloat16 hh = __float2bfloat16(hnew);
    g_h_hi[idx] = hh;
    g_h_lo[idx] = __float2bfloat16(hnew - __bfloat162float(hh));
}

// one warp per (s,b): score = sum_a v[a]*tanh(encW[s,b,a] + hW[b,a])  (HW tanh)
__global__ void scores_kernel(const float* __restrict__ v_attn)
{
    int gid = blockIdx.x * blockDim.x + threadIdx.x;
    int warp = gid >> 5, lane = gid & 31;
    int b = warp & (B_ - 1);
    const float* e = g_encW + (size_t)warp * A_;
    const float* hw = g_hW + (size_t)b * A_;
    float acc = 0.f;
#pragma unroll 4
    for (int a = lane; a < A_; a += 32) {
        float x = e[a] + hw[a], t;
        asm("tanh.approx.f32 %0, %1;" : "=f"(t) : "f"(x));
        acc += v_attn[a] * t;
    }
#pragma unroll
    for (int off = 16; off; off >>= 1)
        acc += __shfl_xor_sync(0xffffffffu, acc, off);
    if (!lane) g_scores[warp] = acc;
}

__global__ void softmax_kernel(float* __restrict__ out_attn, int t)
{
    int b = blockIdx.x * blockDim.x + threadIdx.x;
    if (b >= B_) return;
    float vals[S_];
    float m = -1e30f;
#pragma unroll
    for (int s = 0; s < S_; ++s) { vals[s] = g_scores[s * B_ + b]; m = fmaxf(m, vals[s]); }
    float sum = 0.f;
#pragma unroll
    for (int s = 0; s < S_; ++s) { vals[s] = expf(vals[s] - m); sum += vals[s]; }
    float inv = 1.f / sum;
    float* ao = out_attn + (size_t)(t - 1) * B_ * S_ + (size_t)b * S_;
#pragma unroll
    for (int s = 0; s < S_; ++s) {
        float a = vals[s] * inv;
        g_alpha[s * B_ + b] = a;
        ao[s] = a;
    }
}

__global__ void ctx_kernel()
{
    int idx = blockIdx.x * blockDim.x + threadIdx.x;
    int b = idx >> 10, h = idx & 1023;
    float acc = 0.f;
#pragma unroll
    for (int s = 0; s < S_; ++s)
        acc += g_alpha[s * B_ + b] * g_enc_ops[((size_t)s * B_ + b) * H_ + h];
    __nv_bfloat16 ch = __float2bfloat16(acc);
    g_ctx_hi[idx] = ch;
    g_ctx_lo[idx] = __float2bfloat16(acc - __bfloat162float(ch));
}

// logits = h @ W_out + b_out (K split across 4 groups of 70 threads)
__global__ __launch_bounds__(288) void logits_kernel(
    const float* __restrict__ W_out, const float* __restrict__ b_out,
    const int* __restrict__ target, const int* __restrict__ tf_flag,
    int t, float* __restrict__ out)
{
    __shared__ float sh[H_];
    __shared__ float part[4][VT_];
    __shared__ float sl[VT_];
    int b = blockIdx.x, tid = threadIdx.x;
    for (int i = tid; i < H_; i += 288) sh[i] = g_h[b * H_ + i];
    __syncthreads();
    if (tid < 280) {
        int g = tid / VT_, v = tid - g * VT_;
        float acc = 0.f;
        int k0 = g * (H_ / 4);
#pragma unroll 8
        for (int k = k0; k < k0 + H_ / 4; ++k) acc += sh[k] * W_out[k * VT_ + v];
        part[g][v] = acc;
    }
    __syncthreads();
    if (tid < VT_) {
        float acc = b_out[tid] + part[0][tid] + part[1][tid] + part[2][tid] + part[3][tid];
        sl[tid] = acc;
        out[((size_t)t * B_ + b) * VT_ + tid] = acc;
    }
    __syncthreads();
    if (tid == 0) {
        int x;
        if (*tf_flag) {
            x = target[t * B_ + b];
        } else {
            int best = 0; float bv = sl[0];
            for (int v = 1; v < VT_; ++v)
                if (sl[v] > bv) { bv = sl[v]; best = v; }
            x = best;
        }
        g_x[b] = x;
    }
}

// ---------------- orchestration ----------------
extern "C" void kernel_launch(void* const* d_in, const int* in_sizes, int n_in,
                              void* d_out, int out_size)
{
    const int*   source   = (const int*)  d_in[0];
    const int*   target   = (const int*)  d_in[1];
    const int*   tf       = (const int*)  d_in[2];
    const float* emb_src  = (const float*)d_in[3];
    const float* W_ih_enc = (const float*)d_in[4];
    const float* W_hh_enc = (const float*)d_in[5];
    const float* b_ih_enc = (const float*)d_in[6];
    const float* b_hh_enc = (const float*)d_in[7];
    const float* emb_tgt  = (const float*)d_in[8];
    const float* W_attn   = (const float*)d_in[9];
    const float* b_attn   = (const float*)d_in[10];
    const float* v_attn   = (const float*)d_in[11];
    const float* W_ih_dec = (const float*)d_in[12];
    const float* W_hh_dec = (const float*)d_in[13];
    const float* b_ih_dec = (const float*)d_in[14];
    const float* b_hh_dec = (const float*)d_in[15];
    const float* W_out    = (const float*)d_in[16];
    const float* b_out    = (const float*)d_in[17];

    float* out = (float*)d_out;
    float* out_attn = out + (size_t)T_ * B_ * VT_;

    cudaFuncSetAttribute(hmma_gemm, cudaFuncAttributeMaxDynamicSharedMemorySize, HM_SMEM);

    float *p_tge, *p_tgd, *p_gates, *p_gi, *p_encW, *p_hW;
    cudaGetSymbolAddress((void**)&p_tge,   g_token_gi_enc);
    cudaGetSymbolAddress((void**)&p_tgd,   g_token_gi_dec);
    cudaGetSymbolAddress((void**)&p_gates, g_gates);
    cudaGetSymbolAddress((void**)&p_gi,    g_gi);
    cudaGetSymbolAddress((void**)&p_encW,  g_encW);
    cudaGetSymbolAddress((void**)&p_hW,    g_hW);
    __nv_bfloat16 *p_hhi, *p_hlo, *p_chi, *p_clo, *p_ehi, *p_elo;
    __nv_bfloat16 *p_Whe_h, *p_Whe_l, *p_Whd_h, *p_Whd_l, *p_Wid_h, *p_Wid_l, *p_Wat_h, *p_Wat_l;
    cudaGetSymbolAddress((void**)&p_hhi, g_h_hi);   cudaGetSymbolAddress((void**)&p_hlo, g_h_lo);
    cudaGetSymbolAddress((void**)&p_chi, g_ctx_hi); cudaGetSymbolAddress((void**)&p_clo, g_ctx_lo);
    cudaGetSymbolAddress((void**)&p_ehi, g_enc_hi); cudaGetSymbolAddress((void**)&p_elo, g_enc_lo);
    cudaGetSymbolAddress((void**)&p_Whe_h, g_Whe_hi); cudaGetSymbolAddress((void**)&p_Whe_l, g_Whe_lo);
    cudaGetSymbolAddress((void**)&p_Whd_h, g_Whd_hi); cudaGetSymbolAddress((void**)&p_Whd_l, g_Whd_lo);
    cudaGetSymbolAddress((void**)&p_Wid_h, g_Wid_hi); cudaGetSymbolAddress((void**)&p_Wid_l, g_Wid_lo);
    cudaGetSymbolAddress((void**)&p_Wat_h, g_Wat_hi); cudaGetSymbolAddress((void**)&p_Wat_l, g_Wat_lo);

    const int PW_BLOCKS = (B_ * H_) / 256;

    // ---- prep: init + weight splits + token tables ----
    init_kernel<<<PW_BLOCKS, 256>>>(target, out);
    split_mat<<<(G3H * H_ + 255) / 256, 256>>>(W_hh_enc, H_, H_, p_Whe_h, p_Whe_l, G3H * H_);
    split_mat<<<(G3H * H_ + 255) / 256, 256>>>(W_hh_dec, H_, H_, p_Whd_h, p_Whd_l, G3H * H_);
    split_mat<<<(G3H * H_ + 255) / 256, 256>>>(W_ih_dec, H_ + E_, H_, p_Wid_h, p_Wid_l, G3H * H_);
    transpose_split<<<(A_ * 2 * H_ + 255) / 256, 256>>>(W_attn, p_Wat_h, p_Wat_l);
    gemm_k<1><<<dim3(G3H / 64, 1), 256>>>(
        emb_src, W_ih_enc, b_ih_enc, p_tge, VS_, G3H, E_, E_, E_, G3H);
    gemm_k<1><<<dim3(G3H / 64, 2), 256>>>(
        emb_tgt, W_ih_dec + H_, b_ih_dec, p_tgd, VT_, G3H, E_, E_, H_ + E_, G3H);

    // ---- encoder ----
    for (int s = 0; s < S_; ++s) {
        hmma_gemm<<<dim3(G3H / 128, B_ / 128), 256, HM_SMEM>>>(
            p_hhi, p_hlo, H_, p_Whe_h, p_Whe_l, H_, b_hh_enc, p_gates, G3H, H_);
        enc_pointwise<<<PW_BLOCKS, 256>>>(source, s);
    }

    // ---- attention precompute: enc_ops @ W_attn[H:,:] + b_attn ----
    hmma_gemm<<<dim3(A_ / 128, (S_ * B_) / 128), 256, HM_SMEM>>>(
        p_ehi, p_elo, H_, p_Wat_h + H_, p_Wat_l + H_, 2 * H_, b_attn, p_encW, A_, H_);

    // ---- decoder ----
    for (int t = 1; t < T_; ++t) {
        hmma_gemm<<<dim3(A_ / 128, B_ / 128), 256, HM_SMEM>>>(
            p_hhi, p_hlo, H_, p_Wat_h, p_Wat_l, 2 * H_, nullptr, p_hW, A_, H_);
        scores_kernel<<<(S_ * B_ * 32) / 256, 256>>>(v_attn);
        softmax_kernel<<<2, 256>>>(out_attn, t);
        ctx_kernel<<<PW_BLOCKS, 256>>>();
        hmma_gemm<<<dim3(G3H / 128, B_ / 128), 256, HM_SMEM>>>(
            p_chi, p_clo, H_, p_Wid_h, p_Wid_l, H_, nullptr, p_gi, G3H, H_);
        hmma_gemm<<<dim3(G3H / 128, B_ / 128), 256, HM_SMEM>>>(
            p_hhi, p_hlo, H_, p_Whd_h, p_Whd_l, H_, b_hh_dec, p_gates, G3H, H_);
        dec_pointwise<<<PW_BLOCKS, 256>>>();
        logits_kernel<<<B_, 288>>>(W_out, b_out, target, tf, t, out);
    }
}

// round 9
// speedup vs baseline: 2.4058x; 1.2904x over previous
#include <cuda_runtime.h>
#include <cuda_bf16.h>
#include <cuda_fp16.h>
#include <math.h>
#include <stdint.h>

#define S_ 32
#define T_ 32
#define B_ 512
#define H_ 1024
#define E_ 256
#define A_ 1024
#define VS_ 64
#define VT_ 70
#define G3H (3*H_)
#define START_TOK 1

// ---------------- device scratch (static, no runtime allocation) ----------------
__device__ float g_token_gi_enc[VS_ * G3H];
__device__ float g_token_gi_dec[VT_ * G3H];
__device__ float g_h[B_ * H_];
__device__ float g_gates[B_ * G3H];
__device__ float g_gi[B_ * G3H];
__device__ float g_enc_ops[(size_t)S_ * B_ * H_];
__device__ float g_encW[(size_t)S_ * B_ * A_];
__device__ float g_hW[B_ * A_];
__device__ float g_scores[S_ * B_];
__device__ int   g_x[B_];

// bf16 split activations
__device__ __nv_bfloat16 g_h_hi[B_ * H_],  g_h_lo[B_ * H_];
__device__ __nv_bfloat16 g_ctx_hi[B_ * H_], g_ctx_lo[B_ * H_];
__device__ __nv_bfloat16 g_enc_hi[(size_t)S_ * B_ * H_], g_enc_lo[(size_t)S_ * B_ * H_];
// bf16 split weights (K-major [N,K])
__device__ __nv_bfloat16 g_Whe_hi[G3H * H_], g_Whe_lo[G3H * H_];       // W_hh_enc
__device__ __nv_bfloat16 g_Whd_hi[G3H * H_], g_Whd_lo[G3H * H_];       // W_hh_dec
__device__ __nv_bfloat16 g_Wid_hi[G3H * H_], g_Wid_lo[G3H * H_];       // W_ih_dec[:, :H]
__device__ __nv_bfloat16 g_Wat_hi[A_ * 2 * H_], g_Wat_lo[A_ * 2 * H_]; // W_attn^T [A, 2H]

// ---------------- mma.sync / cp.async helpers (arch-neutral on compute_103) ----------------
__device__ __forceinline__ uint32_t smem_u32(const void* p) {
    uint32_t a;
    asm("{ .reg .u64 t; cvta.to.shared.u64 t, %1; cvt.u32.u64 %0, t; }" : "=r"(a) : "l"(p));
    return a;
}

#define LDSM_X4(r0, r1, r2, r3, addr) \
    asm volatile("ldmatrix.sync.aligned.m8n8.x4.shared.b16 {%0,%1,%2,%3}, [%4];" \
        : "=r"(r0), "=r"(r1), "=r"(r2), "=r"(r3) : "r"(addr))

__device__ __forceinline__ void mma16816(float* d, const uint32_t* a, const uint32_t* b) {
    asm volatile("mma.sync.aligned.m16n8k16.row.col.f32.bf16.bf16.f32 "
        "{%0,%1,%2,%3}, {%4,%5,%6,%7}, {%8,%9}, {%0,%1,%2,%3};"
        : "+f"(d[0]), "+f"(d[1]), "+f"(d[2]), "+f"(d[3])
        : "r"(a[0]), "r"(a[1]), "r"(a[2]), "r"(a[3]), "r"(b[0]), "r"(b[1]));
}

__device__ __forceinline__ void cp16(uint32_t dst, const void* src) {
    asm volatile("cp.async.cg.shared.global [%0], [%1], 16;" :: "r"(dst), "l"(src) : "memory");
}
#define CP_COMMIT() asm volatile("cp.async.commit_group;" ::: "memory")
#define CP_WAIT1()  asm volatile("cp.async.wait_group 1;" ::: "memory")
#define CP_WAIT0()  asm volatile("cp.async.wait_group 0;" ::: "memory")

// ---------------- split-bf16 tensor-core GEMM, cp.async double-buffered ----------------
// C[M,N] = (Ahi+Alo)[M,K] @ (B*hi+B*lo)[N,K]^T + bias  (fp32 out; drops lo*lo)
// Two B/output regions split at column nsplit (per-CTA select; nsplit % 128 == 0).
// M % 128 == 0, N % 128 == 0, K % 64 == 0. 256 threads, 8 warps 4(m)x2(n).
#define PAD_ 72                           // bf16 row stride in smem (64 + 8)
#define TILE_ELEMS (128 * PAD_)           // 9216 bf16 = 18432 B
#define STAGE_BYTES (4 * TILE_ELEMS * 2)  // 73728 B
#define HM_SMEM (2 * STAGE_BYTES)         // 147456 B

__global__ __launch_bounds__(256, 1) void hmma_gemm(
    const __nv_bfloat16* __restrict__ Ahi, const __nv_bfloat16* __restrict__ Alo, int lda,
    const __nv_bfloat16* __restrict__ Bhi, const __nv_bfloat16* __restrict__ Blo, int ldb,
    const float* __restrict__ bias, float* __restrict__ Cp, int ldc,
    const __nv_bfloat16* __restrict__ Bhi2, const __nv_bfloat16* __restrict__ Blo2, int ldb2,
    const float* __restrict__ bias2, float* __restrict__ Cp2, int ldc2,
    int nsplit, int K)
{
    extern __shared__ __nv_bfloat16 sm[];
    const uint32_t sbase = smem_u32(sm);
    const int tid = threadIdx.x, lane = tid & 31, wid = tid >> 5;
    const int wm = wid >> 1, wn = wid & 1;
    const int m0 = blockIdx.y * 128;
    const int n0g = blockIdx.x * 128;

    // region select (whole CTA on one side since nsplit % 128 == 0)
    const __nv_bfloat16 *Bh, *Bl;
    const float* bs; float* Co;
    int ldbx, ldco, ncol0;
    if (n0g < nsplit) { Bh = Bhi;  Bl = Blo;  ldbx = ldb;  bs = bias;  Co = Cp;  ldco = ldc;  ncol0 = n0g; }
    else             { Bh = Bhi2; Bl = Blo2; ldbx = ldb2; bs = bias2; Co = Cp2; ldco = ldc2; ncol0 = n0g - nsplit; }

    float acc[2][8][4];
#pragma unroll
    for (int i = 0; i < 2; ++i)
#pragma unroll
        for (int j = 0; j < 8; ++j)
#pragma unroll
            for (int q = 0; q < 4; ++q) acc[i][j][q] = 0.f;

    const __nv_bfloat16* gA0 = Ahi + (size_t)m0 * lda;
    const __nv_bfloat16* gA1 = Alo + (size_t)m0 * lda;
    const __nv_bfloat16* gB0 = Bh + (size_t)ncol0 * ldbx;
    const __nv_bfloat16* gB1 = Bl + (size_t)ncol0 * ldbx;

    const int lrow = tid >> 3, lq = tid & 7;

    // ldmatrix per-thread base offsets (within one tile)
    const uint32_t aoff = ((uint32_t)(wm * 32 + (lane & 15)) * PAD_ + (lane >> 4) * 8) * 2;
    const uint32_t boff = ((uint32_t)(wn * 64 + (lane & 7) + ((lane & 16) ? 8 : 0)) * PAD_
                          + ((lane >> 3) & 1) * 8) * 2;

    const int nchunks = K >> 6;

    // ---- async load of one 64-k chunk (4 tiles) into a stage ----
    auto load_chunk = [&](uint32_t st, int koff) {
#pragma unroll
        for (int i = 0; i < 4; ++i) {
            const int row = lrow + i * 32;
            const uint32_t so = (uint32_t)(row * PAD_ + lq * 8) * 2;
            cp16(st + so,                      gA0 + (size_t)row * lda  + koff + lq * 8);
            cp16(st + TILE_ELEMS * 2 + so,     gA1 + (size_t)row * lda  + koff + lq * 8);
            cp16(st + 2 * TILE_ELEMS * 2 + so, gB0 + (size_t)row * ldbx + koff + lq * 8);
            cp16(st + 3 * TILE_ELEMS * 2 + so, gB1 + (size_t)row * ldbx + koff + lq * 8);
        }
        CP_COMMIT();
    };

    load_chunk(sbase, 0);

    for (int c = 0; c < nchunks; ++c) {
        if (c + 1 < nchunks) {
            load_chunk(sbase + (uint32_t)((c + 1) & 1) * STAGE_BYTES, (c + 1) << 6);
            CP_WAIT1();
        } else {
            CP_WAIT0();
        }
        __syncthreads();

        const uint32_t st = sbase + (uint32_t)(c & 1) * STAGE_BYTES;
        const uint32_t sA0 = st, sA1 = st + TILE_ELEMS * 2;
        const uint32_t sB0 = st + 2 * TILE_ELEMS * 2, sB1 = st + 3 * TILE_ELEMS * 2;

#pragma unroll
        for (int ks = 0; ks < 4; ++ks) {
            const uint32_t kso = (uint32_t)(ks * 16) * 2;
            uint32_t ah[2][4], al[2][4];
#pragma unroll
            for (int mb = 0; mb < 2; ++mb) {
                const uint32_t off = aoff + (uint32_t)(mb * 16 * PAD_) * 2 + kso;
                LDSM_X4(ah[mb][0], ah[mb][1], ah[mb][2], ah[mb][3], sA0 + off);
                LDSM_X4(al[mb][0], al[mb][1], al[mb][2], al[mb][3], sA1 + off);
            }
            uint32_t bh[8][2], bl[8][2];
#pragma unroll
            for (int p = 0; p < 4; ++p) {
                const uint32_t off = boff + (uint32_t)(p * 16 * PAD_) * 2 + kso;
                LDSM_X4(bh[2*p][0], bh[2*p][1], bh[2*p+1][0], bh[2*p+1][1], sB0 + off);
                LDSM_X4(bl[2*p][0], bl[2*p][1], bl[2*p+1][0], bl[2*p+1][1], sB1 + off);
            }
#pragma unroll
            for (int mb = 0; mb < 2; ++mb)
#pragma unroll
                for (int nb = 0; nb < 8; ++nb) {
                    mma16816(acc[mb][nb], ah[mb], bh[nb]);
                    mma16816(acc[mb][nb], al[mb], bh[nb]);
                    mma16816(acc[mb][nb], ah[mb], bl[nb]);
                }
        }
        __syncthreads();
    }

    // epilogue
    const int mrow = m0 + wm * 32 + (lane >> 2);
    const int ncolb = wn * 64 + (lane & 3) * 2;
#pragma unroll
    for (int mb = 0; mb < 2; ++mb) {
        const int m = mrow + mb * 16;
#pragma unroll
        for (int nb = 0; nb < 8; ++nb) {
            const int nc = ncol0 + ncolb + nb * 8;
            float bx = 0.f, by = 0.f;
            if (bs) { bx = bs[nc]; by = bs[nc + 1]; }
            float* c0 = Co + (size_t)m * ldco + nc;
            float* c1 = Co + (size_t)(m + 8) * ldco + nc;
            c0[0] = acc[mb][nb][0] + bx; c0[1] = acc[mb][nb][1] + by;
            c1[0] = acc[mb][nb][2] + bx; c1[1] = acc[mb][nb][3] + by;
        }
    }
}

// ---------------- fp32 SIMT GEMM (tiny token tables only) ----------------
template <int BNK>
__global__ __launch_bounds__(256) void gemm_k(
    const float* __restrict__ Ap, const float* __restrict__ Bp,
    const float* __restrict__ bias, float* __restrict__ Cp,
    int M, int N, int K, int lda, int ldb, int ldc)
{
    __shared__ float As[32][65];
    __shared__ float Bs[32][65];
    const int tid = threadIdx.x;
    const int tx = tid & 15, ty = tid >> 4;
    const int m0 = blockIdx.y * 64, n0 = blockIdx.x * 64;
    float acc[4][4];
#pragma unroll
    for (int i = 0; i < 4; ++i)
#pragma unroll
        for (int j = 0; j < 4; ++j) acc[i][j] = 0.f;
    for (int kt = 0; kt < K; kt += 32) {
        {
            int r = tid >> 3, c = tid & 7;
#pragma unroll
            for (int p = 0; p < 2; ++p) {
                int row = r + p * 32;
                int m = m0 + row;
                float4 v = make_float4(0.f, 0.f, 0.f, 0.f);
                if (m < M)
                    v = *reinterpret_cast<const float4*>(Ap + (size_t)m * lda + kt + c * 4);
                As[c * 4 + 0][row] = v.x; As[c * 4 + 1][row] = v.y;
                As[c * 4 + 2][row] = v.z; As[c * 4 + 3][row] = v.w;
            }
        }
        {
            int r = tid >> 3, c = tid & 7;
#pragma unroll
            for (int p = 0; p < 2; ++p) {
                int row = r + p * 32;
                float4 v = *reinterpret_cast<const float4*>(Bp + (size_t)(n0 + row) * ldb + kt + c * 4);
                Bs[c * 4 + 0][row] = v.x; Bs[c * 4 + 1][row] = v.y;
                Bs[c * 4 + 2][row] = v.z; Bs[c * 4 + 3][row] = v.w;
            }
        }
        __syncthreads();
#pragma unroll
        for (int kk = 0; kk < 32; ++kk) {
            float a0 = As[kk][ty * 4 + 0], a1 = As[kk][ty * 4 + 1];
            float a2 = As[kk][ty * 4 + 2], a3 = As[kk][ty * 4 + 3];
            float b0 = Bs[kk][tx * 4 + 0], b1 = Bs[kk][tx * 4 + 1];
            float b2 = Bs[kk][tx * 4 + 2], b3 = Bs[kk][tx * 4 + 3];
            acc[0][0] += a0 * b0; acc[0][1] += a0 * b1; acc[0][2] += a0 * b2; acc[0][3] += a0 * b3;
            acc[1][0] += a1 * b0; acc[1][1] += a1 * b1; acc[1][2] += a1 * b2; acc[1][3] += a1 * b3;
            acc[2][0] += a2 * b0; acc[2][1] += a2 * b1; acc[2][2] += a2 * b2; acc[2][3] += a2 * b3;
            acc[3][0] += a3 * b0; acc[3][1] += a3 * b1; acc[3][2] += a3 * b2; acc[3][3] += a3 * b3;
        }
        __syncthreads();
    }
#pragma unroll
    for (int i = 0; i < 4; ++i) {
        int m = m0 + ty * 4 + i;
        if (m < M) {
#pragma unroll
            for (int j = 0; j < 4; ++j) {
                int n = n0 + tx * 4 + j;
                float v = acc[i][j];
                if (bias) v += bias[n];
                Cp[(size_t)m * ldc + n] = v;
            }
        }
    }
}

// ---------------- weight prep ----------------
__global__ void split_mat(const float* __restrict__ src, int ld, int cols,
                          __nv_bfloat16* __restrict__ hi, __nv_bfloat16* __restrict__ lo, int total)
{
    int idx = blockIdx.x * blockDim.x + threadIdx.x;
    if (idx >= total) return;
    int r = idx / cols, c = idx - r * cols;
    float x = src[(size_t)r * ld + c];
    __nv_bfloat16 h = __float2bfloat16(x);
    hi[idx] = h;
    lo[idx] = __float2bfloat16(x - __bfloat162float(h));
}

__global__ void transpose_split(const float* __restrict__ W,
                                __nv_bfloat16* __restrict__ hi, __nv_bfloat16* __restrict__ lo)
{
    int idx = blockIdx.x * blockDim.x + threadIdx.x;   // A_ * 2H
    if (idx >= A_ * 2 * H_) return;
    int n = idx >> 11, k = idx & 2047;
    float x = W[(size_t)k * A_ + n];
    __nv_bfloat16 h = __float2bfloat16(x);
    hi[idx] = h;
    lo[idx] = __float2bfloat16(x - __bfloat162float(h));
}

// ---------------- misc kernels ----------------
__global__ void init_kernel(const int* __restrict__ target, float* __restrict__ out)
{
    int idx = blockIdx.x * blockDim.x + threadIdx.x;
    if (idx < B_ * H_) {
        g_h[idx] = 0.f;
        g_h_hi[idx] = __float2bfloat16(0.f);
        g_h_lo[idx] = __float2bfloat16(0.f);
    }
    if (idx < B_) g_x[idx] = target[idx];
    if (idx < B_ * VT_) {
        int v = idx % VT_;
        out[idx] = (v == START_TOK) ? 1.f : 0.f;
    }
}

__global__ void enc_pointwise(const int* __restrict__ source, int s)
{
    int idx = blockIdx.x * blockDim.x + threadIdx.x;
    int b = idx >> 10, k = idx & 1023;
    int tok = source[s * B_ + b];
    const float* tg = g_token_gi_enc + tok * G3H;
    const float* gh = g_gates + b * G3H;
    float ir = tg[k], iz = tg[H_ + k], in_ = tg[2 * H_ + k];
    float hr = gh[k], hz = gh[H_ + k], hn = gh[2 * H_ + k];
    float r = 1.f / (1.f + expf(-(ir + hr)));
    float z = 1.f / (1.f + expf(-(iz + hz)));
    float n = tanhf(in_ + r * hn);
    float hprev = g_h[idx];
    float hnew = (1.f - z) * n + z * hprev;
    g_h[idx] = hnew;
    size_t eo = ((size_t)s * B_ + b) * H_ + k;
    g_enc_ops[eo] = hnew;
    __nv_bfloat16 hh = __float2bfloat16(hnew);
    __nv_bfloat16 hl = __float2bfloat16(hnew - __bfloat162float(hh));
    g_h_hi[idx] = hh; g_h_lo[idx] = hl;
    g_enc_hi[eo] = hh; g_enc_lo[eo] = hl;
}

__global__ void dec_pointwise()
{
    int idx = blockIdx.x * blockDim.x + threadIdx.x;
    int b = idx >> 10, k = idx & 1023;
    int tok = g_x[b];
    const float* tg = g_token_gi_dec + tok * G3H;
    const float* gi = g_gi + b * G3H;
    const float* gh = g_gates + b * G3H;
    float ir = tg[k] + gi[k];
    float iz = tg[H_ + k] + gi[H_ + k];
    float in_ = tg[2 * H_ + k] + gi[2 * H_ + k];
    float hr = gh[k], hz = gh[H_ + k], hn = gh[2 * H_ + k];
    float r = 1.f / (1.f + expf(-(ir + hr)));
    float z = 1.f / (1.f + expf(-(iz + hz)));
    float n = tanhf(in_ + r * hn);
    float hprev = g_h[idx];
    float hnew = (1.f - z) * n + z * hprev;
    g_h[idx] = hnew;
    __nv_bfloat16 hh = __float2bfloat16(hnew);
    g_h_hi[idx] = hh;
    g_h_lo[idx] = __float2bfloat16(hnew - __bfloat162float(hh));
}

// one warp per (s,b): score = sum_a v[a]*tanh(encW[s,b,a] + hW[b,a])
// tanh via f16x2 MUFU (2 values per op); adds/accumulation stay fp32.
__global__ void scores_kernel(const float* __restrict__ v_attn)
{
    int gid = blockIdx.x * blockDim.x + threadIdx.x;
    int warp = gid >> 5, lane = gid & 31;
    int b = warp & (B_ - 1);
    const float2* e2 = reinterpret_cast<const float2*>(g_encW + (size_t)warp * A_);
    const float2* h2 = reinterpret_cast<const float2*>(g_hW + (size_t)b * A_);
    const float2* v2 = reinterpret_cast<const float2*>(v_attn);
    float acc = 0.f;
#pragma unroll 4
    for (int a2 = lane; a2 < A_ / 2; a2 += 32) {
        float2 ee = e2[a2], hh = h2[a2], vv = v2[a2];
        float x0 = ee.x + hh.x, x1 = ee.y + hh.y;
        uint32_t p, pt;
        asm("cvt.rn.f16x2.f32 %0, %1, %2;" : "=r"(p) : "f"(x1), "f"(x0));  // {hi=x1, lo=x0}
        asm("tanh.approx.f16x2 %0, %1;" : "=r"(pt) : "r"(p));
        __half2 th = *reinterpret_cast<__half2*>(&pt);
        acc += vv.x * __low2float(th) + vv.y * __high2float(th);
    }
#pragma unroll
    for (int off = 16; off; off >>= 1)
        acc += __shfl_xor_sync(0xffffffffu, acc, off);
    if (!lane) g_scores[warp] = acc;
}

// fused: per-b softmax over S=32 + attn output row + ctx = sum_s alpha*enc_ops (+bf16 split)
__global__ __launch_bounds__(256) void softmax_ctx(float* __restrict__ out_attn, int t)
{
    __shared__ float salpha[S_];
    const int b = blockIdx.x, tid = threadIdx.x;
    if (tid < 32) {
        float v = g_scores[tid * B_ + b];
        float m = v;
#pragma unroll
        for (int off = 16; off; off >>= 1)
            m = fmaxf(m, __shfl_xor_sync(0xffffffffu, m, off));
        float e = expf(v - m);
        float sum = e;
#pragma unroll
        for (int off = 16; off; off >>= 1)
            sum += __shfl_xor_sync(0xffffffffu, sum, off);
        float a = e / sum;
        salpha[tid] = a;
        out_attn[(size_t)(t - 1) * B_ * S_ + (size_t)b * S_ + tid] = a;
    }
    __syncthreads();
    const int h = tid * 4;
    float4 acc = make_float4(0.f, 0.f, 0.f, 0.f);
#pragma unroll
    for (int s = 0; s < S_; ++s) {
        float a = salpha[s];
        float4 e = *reinterpret_cast<const float4*>(g_enc_ops + ((size_t)s * B_ + b) * H_ + h);
        acc.x += a * e.x; acc.y += a * e.y; acc.z += a * e.z; acc.w += a * e.w;
    }
    float vals[4] = {acc.x, acc.y, acc.z, acc.w};
#pragma unroll
    for (int i = 0; i < 4; ++i) {
        __nv_bfloat16 ch = __float2bfloat16(vals[i]);
        g_ctx_hi[b * H_ + h + i] = ch;
        g_ctx_lo[b * H_ + h + i] = __float2bfloat16(vals[i] - __bfloat162float(ch));
    }
}

// logits = h @ W_out + b_out (K split across 4 groups of 70 threads)
__global__ __launch_bounds__(288) void logits_kernel(
    const float* __restrict__ W_out, const float* __restrict__ b_out,
    const int* __restrict__ target, const int* __restrict__ tf_flag,
    int t, float* __restrict__ out)
{
    __shared__ float sh[H_];
    __shared__ float part[4][VT_];
    __shared__ float sl[VT_];
    int b = blockIdx.x, tid = threadIdx.x;
    for (int i = tid; i < H_; i += 288) sh[i] = g_h[b * H_ + i];
    __syncthreads();
    if (tid < 280) {
        int g = tid / VT_, v = tid - g * VT_;
        float acc = 0.f;
        int k0 = g * (H_ / 4);
#pragma unroll 8
        for (int k = k0; k < k0 + H_ / 4; ++k) acc += sh[k] * W_out[k * VT_ + v];
        part[g][v] = acc;
    }
    __syncthreads();
    if (tid < VT_) {
        float acc = b_out[tid] + part[0][tid] + part[1][tid] + part[2][tid] + part[3][tid];
        sl[tid] = acc;
        out[((size_t)t * B_ + b) * VT_ + tid] = acc;
    }
    __syncthreads();
    if (tid == 0) {
        int x;
        if (*tf_flag) {
            x = target[t * B_ + b];
        } else {
            int best = 0; float bv = sl[0];
            for (int v = 1; v < VT_; ++v)
                if (sl[v] > bv) { bv = sl[v]; best = v; }
            x = best;
        }
        g_x[b] = x;
    }
}

// ---------------- orchestration ----------------
extern "C" void kernel_launch(void* const* d_in, const int* in_sizes, int n_in,
                              void* d_out, int out_size)
{
    const int*   source   = (const int*)  d_in[0];
    const int*   target   = (const int*)  d_in[1];
    const int*   tf       = (const int*)  d_in[2];
    const float* emb_src  = (const float*)d_in[3];
    const float* W_ih_enc = (const float*)d_in[4];
    const float* W_hh_enc = (const float*)d_in[5];
    const float* b_ih_enc = (const float*)d_in[6];
    const float* b_hh_enc = (const float*)d_in[7];
    const float* emb_tgt  = (const float*)d_in[8];
    const float* W_attn   = (const float*)d_in[9];
    const float* b_attn   = (const float*)d_in[10];
    const float* v_attn   = (const float*)d_in[11];
    const float* W_ih_dec = (const float*)d_in[12];
    const float* W_hh_dec = (const float*)d_in[13];
    const float* b_ih_dec = (const float*)d_in[14];
    const float* b_hh_dec = (const float*)d_in[15];
    const float* W_out    = (const float*)d_in[16];
    const float* b_out    = (const float*)d_in[17];

    float* out = (float*)d_out;
    float* out_attn = out + (size_t)T_ * B_ * VT_;

    cudaFuncSetAttribute(hmma_gemm, cudaFuncAttributeMaxDynamicSharedMemorySize, HM_SMEM);

    float *p_tge, *p_tgd, *p_gates, *p_gi, *p_encW, *p_hW;
    cudaGetSymbolAddress((void**)&p_tge,   g_token_gi_enc);
    cudaGetSymbolAddress((void**)&p_tgd,   g_token_gi_dec);
    cudaGetSymbolAddress((void**)&p_gates, g_gates);
    cudaGetSymbolAddress((void**)&p_gi,    g_gi);
    cudaGetSymbolAddress((void**)&p_encW,  g_encW);
    cudaGetSymbolAddress((void**)&p_hW,    g_hW);
    __nv_bfloat16 *p_hhi, *p_hlo, *p_chi, *p_clo, *p_ehi, *p_elo;
    __nv_bfloat16 *p_Whe_h, *p_Whe_l, *p_Whd_h, *p_Whd_l, *p_Wid_h, *p_Wid_l, *p_Wat_h, *p_Wat_l;
    cudaGetSymbolAddress((void**)&p_hhi, g_h_hi);   cudaGetSymbolAddress((void**)&p_hlo, g_h_lo);
    cudaGetSymbolAddress((void**)&p_chi, g_ctx_hi); cudaGetSymbolAddress((void**)&p_clo, g_ctx_lo);
    cudaGetSymbolAddress((void**)&p_ehi, g_enc_hi); cudaGetSymbolAddress((void**)&p_elo, g_enc_lo);
    cudaGetSymbolAddress((void**)&p_Whe_h, g_Whe_hi); cudaGetSymbolAddress((void**)&p_Whe_l, g_Whe_lo);
    cudaGetSymbolAddress((void**)&p_Whd_h, g_Whd_hi); cudaGetSymbolAddress((void**)&p_Whd_l, g_Whd_lo);
    cudaGetSymbolAddress((void**)&p_Wid_h, g_Wid_hi); cudaGetSymbolAddress((void**)&p_Wid_l, g_Wid_lo);
    cudaGetSymbolAddress((void**)&p_Wat_h, g_Wat_hi); cudaGetSymbolAddress((void**)&p_Wat_l, g_Wat_lo);

    const int PW_BLOCKS = (B_ * H_) / 256;
    const int NOSPLIT = 1 << 30;

    // ---- prep: init + weight splits + token tables ----
    init_kernel<<<PW_BLOCKS, 256>>>(target, out);
    split_mat<<<(G3H * H_ + 255) / 256, 256>>>(W_hh_enc, H_, H_, p_Whe_h, p_Whe_l, G3H * H_);
    split_mat<<<(G3H * H_ + 255) / 256, 256>>>(W_hh_dec, H_, H_, p_Whd_h, p_Whd_l, G3H * H_);
    split_mat<<<(G3H * H_ + 255) / 256, 256>>>(W_ih_dec, H_ + E_, H_, p_Wid_h, p_Wid_l, G3H * H_);
    transpose_split<<<(A_ * 2 * H_ + 255) / 256, 256>>>(W_attn, p_Wat_h, p_Wat_l);
    gemm_k<1><<<dim3(G3H / 64, 1), 256>>>(
        emb_src, W_ih_enc, b_ih_enc, p_tge, VS_, G3H, E_, E_, E_, G3H);
    gemm_k<1><<<dim3(G3H / 64, 2), 256>>>(
        emb_tgt, W_ih_dec + H_, b_ih_dec, p_tgd, VT_, G3H, E_, E_, H_ + E_, G3H);

    // ---- encoder ----
    for (int s = 0; s < S_; ++s) {
        hmma_gemm<<<dim3(G3H / 128, B_ / 128), 256, HM_SMEM>>>(
            p_hhi, p_hlo, H_,
            p_Whe_h, p_Whe_l, H_, b_hh_enc, p_gates, G3H,
            nullptr, nullptr, 0, nullptr, nullptr, 0,
            NOSPLIT, H_);
        enc_pointwise<<<PW_BLOCKS, 256>>>(source, s);
    }

    // ---- attention precompute: enc_ops @ W_attn[H:,:] + b_attn ----
    hmma_gemm<<<dim3(A_ / 128, (S_ * B_) / 128), 256, HM_SMEM>>>(
        p_ehi, p_elo, H_,
        p_Wat_h + H_, p_Wat_l + H_, 2 * H_, b_attn, p_encW, A_,
        nullptr, nullptr, 0, nullptr, nullptr, 0,
        NOSPLIT, H_);

    // ---- decoder ----
    for (int t = 1; t < T_; ++t) {
        // fused [hW | gh]: N = A + 3H = 4096, 128 CTAs, one wave
        hmma_gemm<<<dim3((A_ + G3H) / 128, B_ / 128), 256, HM_SMEM>>>(
            p_hhi, p_hlo, H_,
            p_Wat_h, p_Wat_l, 2 * H_, nullptr, p_hW, A_,
            p_Whd_h, p_Whd_l, H_, b_hh_dec, p_gates, G3H,
            A_, H_);
        scores_kernel<<<(S_ * B_ * 32) / 256, 256>>>(v_attn);
        softmax_ctx<<<B_, 256>>>(out_attn, t);
        hmma_gemm<<<dim3(G3H / 128, B_ / 128), 256, HM_SMEM>>>(
            p_chi, p_clo, H_,
            p_Wid_h, p_Wid_l, H_, nullptr, p_gi, G3H,
            nullptr, nullptr, 0, nullptr, nullptr, 0,
            NOSPLIT, H_);
        dec_pointwise<<<PW_BLOCKS, 256>>>();
        logits_kernel<<<B_, 288>>>(W_out, b_out, target, tf, t, out);
    }
}

// round 10
// speedup vs baseline: 2.4303x; 1.0102x over previous
#include <cuda_runtime.h>
#include <cuda_bf16.h>
#include <cuda_fp16.h>
#include <math.h>
#include <stdint.h>

#define S_ 32
#define T_ 32
#define B_ 512
#define H_ 1024
#define E_ 256
#define A_ 1024
#define VS_ 64
#define VT_ 70
#define G3H (3*H_)
#define START_TOK 1

// ---------------- device scratch (static, no runtime allocation) ----------------
__device__ float g_token_gi_enc[VS_ * G3H];
__device__ float g_token_gi_dec[VT_ * G3H];
__device__ float g_h[B_ * H_];
__device__ float g_gates[B_ * G3H];
__device__ float g_gi[B_ * G3H];
__device__ float g_enc_ops[(size_t)S_ * B_ * H_];
__device__ float g_encW[(size_t)S_ * B_ * A_];
__device__ float g_hW[B_ * A_];
__device__ int   g_x[B_];

// bf16 split activations
__device__ __nv_bfloat16 g_h_hi[B_ * H_],  g_h_lo[B_ * H_];
__device__ __nv_bfloat16 g_ctx_hi[B_ * H_], g_ctx_lo[B_ * H_];
__device__ __nv_bfloat16 g_enc_hi[(size_t)S_ * B_ * H_], g_enc_lo[(size_t)S_ * B_ * H_];
// bf16 split weights (K-major [N,K])
__device__ __nv_bfloat16 g_Whe_hi[G3H * H_], g_Whe_lo[G3H * H_];       // W_hh_enc
__device__ __nv_bfloat16 g_Whd_hi[G3H * H_], g_Whd_lo[G3H * H_];       // W_hh_dec
__device__ __nv_bfloat16 g_Wid_hi[G3H * H_], g_Wid_lo[G3H * H_];       // W_ih_dec[:, :H]
__device__ __nv_bfloat16 g_Wat_hi[A_ * 2 * H_], g_Wat_lo[A_ * 2 * H_]; // W_attn^T [A, 2H]

// ---------------- mma.sync / cp.async helpers (arch-neutral on compute_103) ----------------
__device__ __forceinline__ uint32_t smem_u32(const void* p) {
    uint32_t a;
    asm("{ .reg .u64 t; cvta.to.shared.u64 t, %1; cvt.u32.u64 %0, t; }" : "=r"(a) : "l"(p));
    return a;
}

#define LDSM_X4(r0, r1, r2, r3, addr) \
    asm volatile("ldmatrix.sync.aligned.m8n8.x4.shared.b16 {%0,%1,%2,%3}, [%4];" \
        : "=r"(r0), "=r"(r1), "=r"(r2), "=r"(r3) : "r"(addr))

__device__ __forceinline__ void mma16816(float* d, const uint32_t* a, const uint32_t* b) {
    asm volatile("mma.sync.aligned.m16n8k16.row.col.f32.bf16.bf16.f32 "
        "{%0,%1,%2,%3}, {%4,%5,%6,%7}, {%8,%9}, {%0,%1,%2,%3};"
        : "+f"(d[0]), "+f"(d[1]), "+f"(d[2]), "+f"(d[3])
        : "r"(a[0]), "r"(a[1]), "r"(a[2]), "r"(a[3]), "r"(b[0]), "r"(b[1]));
}

__device__ __forceinline__ void cp16(uint32_t dst, const void* src) {
    asm volatile("cp.async.cg.shared.global [%0], [%1], 16;" :: "r"(dst), "l"(src) : "memory");
}
#define CP_COMMIT() asm volatile("cp.async.commit_group;" ::: "memory")
#define CP_WAIT1()  asm volatile("cp.async.wait_group 1;" ::: "memory")
#define CP_WAIT0()  asm volatile("cp.async.wait_group 0;" ::: "memory")

// packed f16x2 tanh: adds/accumulation fp32, only tanh through MUFU f16x2
__device__ __forceinline__ void tanh2(float x0, float x1, float& t0, float& t1) {
    uint32_t p, pt;
    asm("cvt.rn.f16x2.f32 %0, %1, %2;" : "=r"(p) : "f"(x1), "f"(x0));
    asm("tanh.approx.f16x2 %0, %1;" : "=r"(pt) : "r"(p));
    __half2 th = *reinterpret_cast<__half2*>(&pt);
    t0 = __low2float(th); t1 = __high2float(th);
}

// ---------------- split-bf16 tensor-core GEMM, cp.async double-buffered ----------------
// C[M,N] = (Ahi+Alo)[M,K] @ (B*hi+B*lo)[N,K]^T + bias  (fp32 out; drops lo*lo)
// Two B/output regions split at column nsplit (per-CTA select; nsplit % 128 == 0).
// M % 128 == 0, N % 128 == 0, K % 64 == 0. 256 threads, 8 warps 4(m)x2(n).
#define PAD_ 72                           // bf16 row stride in smem (64 + 8)
#define TILE_ELEMS (128 * PAD_)           // 9216 bf16 = 18432 B
#define STAGE_BYTES (4 * TILE_ELEMS * 2)  // 73728 B
#define HM_SMEM (2 * STAGE_BYTES)         // 147456 B

__global__ __launch_bounds__(256, 1) void hmma_gemm(
    const __nv_bfloat16* __restrict__ Ahi, const __nv_bfloat16* __restrict__ Alo, int lda,
    const __nv_bfloat16* __restrict__ Bhi, const __nv_bfloat16* __restrict__ Blo, int ldb,
    const float* __restrict__ bias, float* __restrict__ Cp, int ldc,
    const __nv_bfloat16* __restrict__ Bhi2, const __nv_bfloat16* __restrict__ Blo2, int ldb2,
    const float* __restrict__ bias2, float* __restrict__ Cp2, int ldc2,
    int nsplit, int K)
{
    extern __shared__ __nv_bfloat16 sm[];
    const uint32_t sbase = smem_u32(sm);
    const int tid = threadIdx.x, lane = tid & 31, wid = tid >> 5;
    const int wm = wid >> 1, wn = wid & 1;
    const int m0 = blockIdx.y * 128;
    const int n0g = blockIdx.x * 128;

    // region select (whole CTA on one side since nsplit % 128 == 0)
    const __nv_bfloat16 *Bh, *Bl;
    const float* bs; float* Co;
    int ldbx, ldco, ncol0;
    if (n0g < nsplit) { Bh = Bhi;  Bl = Blo;  ldbx = ldb;  bs = bias;  Co = Cp;  ldco = ldc;  ncol0 = n0g; }
    else             { Bh = Bhi2; Bl = Blo2; ldbx = ldb2; bs = bias2; Co = Cp2; ldco = ldc2; ncol0 = n0g - nsplit; }

    float acc[2][8][4];
#pragma unroll
    for (int i = 0; i < 2; ++i)
#pragma unroll
        for (int j = 0; j < 8; ++j)
#pragma unroll
            for (int q = 0; q < 4; ++q) acc[i][j][q] = 0.f;

    const __nv_bfloat16* gA0 = Ahi + (size_t)m0 * lda;
    const __nv_bfloat16* gA1 = Alo + (size_t)m0 * lda;
    const __nv_bfloat16* gB0 = Bh + (size_t)ncol0 * ldbx;
    const __nv_bfloat16* gB1 = Bl + (size_t)ncol0 * ldbx;

    const int lrow = tid >> 3, lq = tid & 7;

    // ldmatrix per-thread base offsets (within one tile)
    const uint32_t aoff = ((uint32_t)(wm * 32 + (lane & 15)) * PAD_ + (lane >> 4) * 8) * 2;
    const uint32_t boff = ((uint32_t)(wn * 64 + (lane & 7) + ((lane & 16) ? 8 : 0)) * PAD_
                          + ((lane >> 3) & 1) * 8) * 2;

    const int nchunks = K >> 6;

    // ---- async load of one 64-k chunk (4 tiles) into a stage ----
    auto load_chunk = [&](uint32_t st, int koff) {
#pragma unroll
        for (int i = 0; i < 4; ++i) {
            const int row = lrow + i * 32;
            const uint32_t so = (uint32_t)(row * PAD_ + lq * 8) * 2;
            cp16(st + so,                      gA0 + (size_t)row * lda  + koff + lq * 8);
            cp16(st + TILE_ELEMS * 2 + so,     gA1 + (size_t)row * lda  + koff + lq * 8);
            cp16(st + 2 * TILE_ELEMS * 2 + so, gB0 + (size_t)row * ldbx + koff + lq * 8);
            cp16(st + 3 * TILE_ELEMS * 2 + so, gB1 + (size_t)row * ldbx + koff + lq * 8);
        }
        CP_COMMIT();
    };

    load_chunk(sbase, 0);

    for (int c = 0; c < nchunks; ++c) {
        if (c + 1 < nchunks) {
            load_chunk(sbase + (uint32_t)((c + 1) & 1) * STAGE_BYTES, (c + 1) << 6);
            CP_WAIT1();
        } else {
            CP_WAIT0();
        }
        __syncthreads();

        const uint32_t st = sbase + (uint32_t)(c & 1) * STAGE_BYTES;
        const uint32_t sA0 = st, sA1 = st + TILE_ELEMS * 2;
        const uint32_t sB0 = st + 2 * TILE_ELEMS * 2, sB1 = st + 3 * TILE_ELEMS * 2;

#pragma unroll
        for (int ks = 0; ks < 4; ++ks) {
            const uint32_t kso = (uint32_t)(ks * 16) * 2;
            uint32_t ah[2][4], al[2][4];
#pragma unroll
            for (int mb = 0; mb < 2; ++mb) {
                const uint32_t off = aoff + (uint32_t)(mb * 16 * PAD_) * 2 + kso;
                LDSM_X4(ah[mb][0], ah[mb][1], ah[mb][2], ah[mb][3], sA0 + off);
                LDSM_X4(al[mb][0], al[mb][1], al[mb][2], al[mb][3], sA1 + off);
            }
            uint32_t bh[8][2], bl[8][2];
#pragma unroll
            for (int p = 0; p < 4; ++p) {
                const uint32_t off = boff + (uint32_t)(p * 16 * PAD_) * 2 + kso;
                LDSM_X4(bh[2*p][0], bh[2*p][1], bh[2*p+1][0], bh[2*p+1][1], sB0 + off);
                LDSM_X4(bl[2*p][0], bl[2*p][1], bl[2*p+1][0], bl[2*p+1][1], sB1 + off);
            }
#pragma unroll
            for (int mb = 0; mb < 2; ++mb)
#pragma unroll
                for (int nb = 0; nb < 8; ++nb) {
                    mma16816(acc[mb][nb], ah[mb], bh[nb]);
                    mma16816(acc[mb][nb], al[mb], bh[nb]);
                    mma16816(acc[mb][nb], ah[mb], bl[nb]);
                }
        }
        __syncthreads();
    }

    // epilogue
    const int mrow = m0 + wm * 32 + (lane >> 2);
    const int ncolb = wn * 64 + (lane & 3) * 2;
#pragma unroll
    for (int mb = 0; mb < 2; ++mb) {
        const int m = mrow + mb * 16;
#pragma unroll
        for (int nb = 0; nb < 8; ++nb) {
            const int nc = ncol0 + ncolb + nb * 8;
            float bx = 0.f, by = 0.f;
            if (bs) { bx = bs[nc]; by = bs[nc + 1]; }
            float* c0 = Co + (size_t)m * ldco + nc;
            float* c1 = Co + (size_t)(m + 8) * ldco + nc;
            c0[0] = acc[mb][nb][0] + bx; c0[1] = acc[mb][nb][1] + by;
            c1[0] = acc[mb][nb][2] + bx; c1[1] = acc[mb][nb][3] + by;
        }
    }
}

// ---------------- fp32 SIMT GEMM (tiny token tables only) ----------------
template <int BNK>
__global__ __launch_bounds__(256) void gemm_k(
    const float* __restrict__ Ap, const float* __restrict__ Bp,
    const float* __restrict__ bias, float* __restrict__ Cp,
    int M, int N, int K, int lda, int ldb, int ldc)
{
    __shared__ float As[32][65];
    __shared__ float Bs[32][65];
    const int tid = threadIdx.x;
    const int tx = tid & 15, ty = tid >> 4;
    const int m0 = blockIdx.y * 64, n0 = blockIdx.x * 64;
    float acc[4][4];
#pragma unroll
    for (int i = 0; i < 4; ++i)
#pragma unroll
        for (int j = 0; j < 4; ++j) acc[i][j] = 0.f;
    for (int kt = 0; kt < K; kt += 32) {
        {
            int r = tid >> 3, c = tid & 7;
#pragma unroll
            for (int p = 0; p < 2; ++p) {
                int row = r + p * 32;
                int m = m0 + row;
                float4 v = make_float4(0.f, 0.f, 0.f, 0.f);
                if (m < M)
                    v = *reinterpret_cast<const float4*>(Ap + (size_t)m * lda + kt + c * 4);
                As[c * 4 + 0][row] = v.x; As[c * 4 + 1][row] = v.y;
                As[c * 4 + 2][row] = v.z; As[c * 4 + 3][row] = v.w;
            }
        }
        {
            int r = tid >> 3, c = tid & 7;
#pragma unroll
            for (int p = 0; p < 2; ++p) {
                int row = r + p * 32;
                float4 v = *reinterpret_cast<const float4*>(Bp + (size_t)(n0 + row) * ldb + kt + c * 4);
                Bs[c * 4 + 0][row] = v.x; Bs[c * 4 + 1][row] = v.y;
                Bs[c * 4 + 2][row] = v.z; Bs[c * 4 + 3][row] = v.w;
            }
        }
        __syncthreads();
#pragma unroll
        for (int kk = 0; kk < 32; ++kk) {
            float a0 = As[kk][ty * 4 + 0], a1 = As[kk][ty * 4 + 1];
            float a2 = As[kk][ty * 4 + 2], a3 = As[kk][ty * 4 + 3];
            float b0 = Bs[kk][tx * 4 + 0], b1 = Bs[kk][tx * 4 + 1];
            float b2 = Bs[kk][tx * 4 + 2], b3 = Bs[kk][tx * 4 + 3];
            acc[0][0] += a0 * b0; acc[0][1] += a0 * b1; acc[0][2] += a0 * b2; acc[0][3] += a0 * b3;
            acc[1][0] += a1 * b0; acc[1][1] += a1 * b1; acc[1][2] += a1 * b2; acc[1][3] += a1 * b3;
            acc[2][0] += a2 * b0; acc[2][1] += a2 * b1; acc[2][2] += a2 * b2; acc[2][3] += a2 * b3;
            acc[3][0] += a3 * b0; acc[3][1] += a3 * b1; acc[3][2] += a3 * b2; acc[3][3] += a3 * b3;
        }
        __syncthreads();
    }
#pragma unroll
    for (int i = 0; i < 4; ++i) {
        int m = m0 + ty * 4 + i;
        if (m < M) {
#pragma unroll
            for (int j = 0; j < 4; ++j) {
                int n = n0 + tx * 4 + j;
                float v = acc[i][j];
                if (bias) v += bias[n];
                Cp[(size_t)m * ldc + n] = v;
            }
        }
    }
}

// ---------------- weight prep ----------------
__global__ void split_mat(const float* __restrict__ src, int ld, int cols,
                          __nv_bfloat16* __restrict__ hi, __nv_bfloat16* __restrict__ lo, int total)
{
    int idx = blockIdx.x * blockDim.x + threadIdx.x;
    if (idx >= total) return;
    int r = idx / cols, c = idx - r * cols;
    float x = src[(size_t)r * ld + c];
    __nv_bfloat16 h = __float2bfloat16(x);
    hi[idx] = h;
    lo[idx] = __float2bfloat16(x - __bfloat162float(h));
}

__global__ void transpose_split(const float* __restrict__ W,
                                __nv_bfloat16* __restrict__ hi, __nv_bfloat16* __restrict__ lo)
{
    int idx = blockIdx.x * blockDim.x + threadIdx.x;   // A_ * 2H
    if (idx >= A_ * 2 * H_) return;
    int n = idx >> 11, k = idx & 2047;
    float x = W[(size_t)k * A_ + n];
    __nv_bfloat16 h = __float2bfloat16(x);
    hi[idx] = h;
    lo[idx] = __float2bfloat16(x - __bfloat162float(h));
}

// ---------------- misc kernels ----------------
__global__ void init_kernel(const int* __restrict__ target, float* __restrict__ out)
{
    int idx = blockIdx.x * blockDim.x + threadIdx.x;
    if (idx < B_ * H_) {
        g_h[idx] = 0.f;
        g_h_hi[idx] = __float2bfloat16(0.f);
        g_h_lo[idx] = __float2bfloat16(0.f);
    }
    if (idx < B_) g_x[idx] = target[idx];
    if (idx < B_ * VT_) {
        int v = idx % VT_;
        out[idx] = (v == START_TOK) ? 1.f : 0.f;
    }
}

__global__ void enc_pointwise(const int* __restrict__ source, int s)
{
    int idx = blockIdx.x * blockDim.x + threadIdx.x;
    int b = idx >> 10, k = idx & 1023;
    int tok = source[s * B_ + b];
    const float* tg = g_token_gi_enc + tok * G3H;
    const float* gh = g_gates + b * G3H;
    float ir = tg[k], iz = tg[H_ + k], in_ = tg[2 * H_ + k];
    float hr = gh[k], hz = gh[H_ + k], hn = gh[2 * H_ + k];
    float r = 1.f / (1.f + expf(-(ir + hr)));
    float z = 1.f / (1.f + expf(-(iz + hz)));
    float n = tanhf(in_ + r * hn);
    float hprev = g_h[idx];
    float hnew = (1.f - z) * n + z * hprev;
    g_h[idx] = hnew;
    size_t eo = ((size_t)s * B_ + b) * H_ + k;
    g_enc_ops[eo] = hnew;
    __nv_bfloat16 hh = __float2bfloat16(hnew);
    __nv_bfloat16 hl = __float2bfloat16(hnew - __bfloat162float(hh));
    g_h_hi[idx] = hh; g_h_lo[idx] = hl;
    g_enc_hi[eo] = hh; g_enc_lo[eo] = hl;
}

// fused attention: one CTA per b. scores (f16x2 tanh) + softmax + attn-out + ctx (+bf16 split)
__global__ __launch_bounds__(256) void attn_fused(
    const float* __restrict__ v_attn, float* __restrict__ out_attn, int t)
{
    __shared__ float shw[A_];     // hW row for this b
    __shared__ float ssc[S_];     // raw scores
    __shared__ float sal[S_];     // alpha
    const int b = blockIdx.x, tid = threadIdx.x;
    const int wid = tid >> 5, lane = tid & 31;

    for (int i = tid; i < A_; i += 256) shw[i] = g_hW[(size_t)b * A_ + i];
    __syncthreads();

    const float2* h2 = reinterpret_cast<const float2*>(shw);
    const float2* v2 = reinterpret_cast<const float2*>(v_attn);
    // each warp computes 4 source positions
#pragma unroll
    for (int si = 0; si < 4; ++si) {
        const int s = wid * 4 + si;
        const float2* e2 = reinterpret_cast<const float2*>(g_encW + ((size_t)s * B_ + b) * A_);
        float acc = 0.f;
#pragma unroll 4
        for (int a2 = lane; a2 < A_ / 2; a2 += 32) {
            float2 ee = e2[a2], hh = h2[a2], vv = v2[a2];
            float t0, t1;
            tanh2(ee.x + hh.x, ee.y + hh.y, t0, t1);
            acc += vv.x * t0 + vv.y * t1;
        }
#pragma unroll
        for (int off = 16; off; off >>= 1)
            acc += __shfl_xor_sync(0xffffffffu, acc, off);
        if (!lane) ssc[s] = acc;
    }
    __syncthreads();

    if (tid < 32) {
        float v = ssc[tid];
        float m = v;
#pragma unroll
        for (int off = 16; off; off >>= 1)
            m = fmaxf(m, __shfl_xor_sync(0xffffffffu, m, off));
        float e = expf(v - m);
        float sum = e;
#pragma unroll
        for (int off = 16; off; off >>= 1)
            sum += __shfl_xor_sync(0xffffffffu, sum, off);
        float a = e / sum;
        sal[tid] = a;
        out_attn[(size_t)(t - 1) * B_ * S_ + (size_t)b * S_ + tid] = a;
    }
    __syncthreads();

    const int h = tid * 4;
    float4 acc = make_float4(0.f, 0.f, 0.f, 0.f);
#pragma unroll
    for (int s = 0; s < S_; ++s) {
        float a = sal[s];
        float4 e = *reinterpret_cast<const float4*>(g_enc_ops + ((size_t)s * B_ + b) * H_ + h);
        acc.x += a * e.x; acc.y += a * e.y; acc.z += a * e.z; acc.w += a * e.w;
    }
    float vals[4] = {acc.x, acc.y, acc.z, acc.w};
#pragma unroll
    for (int i = 0; i < 4; ++i) {
        __nv_bfloat16 ch = __float2bfloat16(vals[i]);
        g_ctx_hi[b * H_ + h + i] = ch;
        g_ctx_lo[b * H_ + h + i] = __float2bfloat16(vals[i] - __bfloat162float(ch));
    }
}

// fused decoder pointwise + logits: one CTA per b; h stays in smem between phases
__global__ __launch_bounds__(288) void dec_fused(
    const float* __restrict__ W_out, const float* __restrict__ b_out,
    const int* __restrict__ target, const int* __restrict__ tf_flag,
    int t, float* __restrict__ out)
{
    __shared__ float sh[H_];
    __shared__ float part[4][VT_];
    __shared__ float sl[VT_];
    const int b = blockIdx.x, tid = threadIdx.x;
    const int tok = g_x[b];
    const float* tg = g_token_gi_dec + tok * G3H;
    const float* gi = g_gi + (size_t)b * G3H;
    const float* gh = g_gates + (size_t)b * G3H;

    for (int k = tid; k < H_; k += 288) {
        float ir = tg[k] + gi[k];
        float iz = tg[H_ + k] + gi[H_ + k];
        float in_ = tg[2 * H_ + k] + gi[2 * H_ + k];
        float hr = gh[k], hz = gh[H_ + k], hn = gh[2 * H_ + k];
        float r = 1.f / (1.f + expf(-(ir + hr)));
        float z = 1.f / (1.f + expf(-(iz + hz)));
        float n = tanhf(in_ + r * hn);
        float hprev = g_h[(size_t)b * H_ + k];
        float hnew = (1.f - z) * n + z * hprev;
        sh[k] = hnew;
        g_h[(size_t)b * H_ + k] = hnew;
        __nv_bfloat16 hh = __float2bfloat16(hnew);
        g_h_hi[b * H_ + k] = hh;
        g_h_lo[b * H_ + k] = __float2bfloat16(hnew - __bfloat162float(hh));
    }
    __syncthreads();

    if (tid < 280) {
        int g = tid / VT_, v = tid - g * VT_;
        float acc = 0.f;
        int k0 = g * (H_ / 4);
#pragma unroll 8
        for (int k = k0; k < k0 + H_ / 4; ++k) acc += sh[k] * W_out[k * VT_ + v];
        part[g][v] = acc;
    }
    __syncthreads();
    if (tid < VT_) {
        float acc = b_out[tid] + part[0][tid] + part[1][tid] + part[2][tid] + part[3][tid];
        sl[tid] = acc;
        out[((size_t)t * B_ + b) * VT_ + tid] = acc;
    }
    __syncthreads();
    if (tid == 0) {
        int x;
        if (*tf_flag) {
            x = target[t * B_ + b];
        } else {
            int best = 0; float bv = sl[0];
            for (int v = 1; v < VT_; ++v)
                if (sl[v] > bv) { bv = sl[v]; best = v; }
            x = best;
        }
        g_x[b] = x;
    }
}

// ---------------- orchestration ----------------
extern "C" void kernel_launch(void* const* d_in, const int* in_sizes, int n_in,
                              void* d_out, int out_size)
{
    const int*   source   = (const int*)  d_in[0];
    const int*   target   = (const int*)  d_in[1];
    const int*   tf       = (const int*)  d_in[2];
    const float* emb_src  = (const float*)d_in[3];
    const float* W_ih_enc = (const float*)d_in[4];
    const float* W_hh_enc = (const float*)d_in[5];
    const float* b_ih_enc = (const float*)d_in[6];
    const float* b_hh_enc = (const float*)d_in[7];
    const float* emb_tgt  = (const float*)d_in[8];
    const float* W_attn   = (const float*)d_in[9];
    const float* b_attn   = (const float*)d_in[10];
    const float* v_attn   = (const float*)d_in[11];
    const float* W_ih_dec = (const float*)d_in[12];
    const float* W_hh_dec = (const float*)d_in[13];
    const float* b_ih_dec = (const float*)d_in[14];
    const float* b_hh_dec = (const float*)d_in[15];
    const float* W_out    = (const float*)d_in[16];
    const float* b_out    = (const float*)d_in[17];

    float* out = (float*)d_out;
    float* out_attn = out + (size_t)T_ * B_ * VT_;

    cudaFuncSetAttribute(hmma_gemm, cudaFuncAttributeMaxDynamicSharedMemorySize, HM_SMEM);

    float *p_tge, *p_tgd, *p_gates, *p_gi, *p_encW, *p_hW;
    cudaGetSymbolAddress((void**)&p_tge,   g_token_gi_enc);
    cudaGetSymbolAddress((void**)&p_tgd,   g_token_gi_dec);
    cudaGetSymbolAddress((void**)&p_gates, g_gates);
    cudaGetSymbolAddress((void**)&p_gi,    g_gi);
    cudaGetSymbolAddress((void**)&p_encW,  g_encW);
    cudaGetSymbolAddress((void**)&p_hW,    g_hW);
    __nv_bfloat16 *p_hhi, *p_hlo, *p_chi, *p_clo, *p_ehi, *p_elo;
    __nv_bfloat16 *p_Whe_h, *p_Whe_l, *p_Whd_h, *p_Whd_l, *p_Wid_h, *p_Wid_l, *p_Wat_h, *p_Wat_l;
    cudaGetSymbolAddress((void**)&p_hhi, g_h_hi);   cudaGetSymbolAddress((void**)&p_hlo, g_h_lo);
    cudaGetSymbolAddress((void**)&p_chi, g_ctx_hi); cudaGetSymbolAddress((void**)&p_clo, g_ctx_lo);
    cudaGetSymbolAddress((void**)&p_ehi, g_enc_hi); cudaGetSymbolAddress((void**)&p_elo, g_enc_lo);
    cudaGetSymbolAddress((void**)&p_Whe_h, g_Whe_hi); cudaGetSymbolAddress((void**)&p_Whe_l, g_Whe_lo);
    cudaGetSymbolAddress((void**)&p_Whd_h, g_Whd_hi); cudaGetSymbolAddress((void**)&p_Whd_l, g_Whd_lo);
    cudaGetSymbolAddress((void**)&p_Wid_h, g_Wid_hi); cudaGetSymbolAddress((void**)&p_Wid_l, g_Wid_lo);
    cudaGetSymbolAddress((void**)&p_Wat_h, g_Wat_hi); cudaGetSymbolAddress((void**)&p_Wat_l, g_Wat_lo);

    const int PW_BLOCKS = (B_ * H_) / 256;
    const int NOSPLIT = 1 << 30;

    // ---- prep (ordered so launch index 5 = encoder hmma_gemm, for ncu -s 5) ----
    init_kernel<<<PW_BLOCKS, 256>>>(target, out);                          // 0
    gemm_k<1><<<dim3(G3H / 64, 1), 256>>>(
        emb_src, W_ih_enc, b_ih_enc, p_tge, VS_, G3H, E_, E_, E_, G3H);    // 1
    split_mat<<<(G3H * H_ + 255) / 256, 256>>>(W_hh_enc, H_, H_, p_Whe_h, p_Whe_l, G3H * H_); // 2

    // ---- encoder (launches 3,4,5,...) ----
    for (int s = 0; s < S_; ++s) {
        hmma_gemm<<<dim3(G3H / 128, B_ / 128), 256, HM_SMEM>>>(
            p_hhi, p_hlo, H_,
            p_Whe_h, p_Whe_l, H_, b_hh_enc, p_gates, G3H,
            nullptr, nullptr, 0, nullptr, nullptr, 0,
            NOSPLIT, H_);
        enc_pointwise<<<PW_BLOCKS, 256>>>(source, s);
    }

    // ---- remaining prep (independent of encoder; needed by decoder/encW) ----
    split_mat<<<(G3H * H_ + 255) / 256, 256>>>(W_hh_dec, H_, H_, p_Whd_h, p_Whd_l, G3H * H_);
    split_mat<<<(G3H * H_ + 255) / 256, 256>>>(W_ih_dec, H_ + E_, H_, p_Wid_h, p_Wid_l, G3H * H_);
    transpose_split<<<(A_ * 2 * H_ + 255) / 256, 256>>>(W_attn, p_Wat_h, p_Wat_l);
    gemm_k<1><<<dim3(G3H / 64, 2), 256>>>(
        emb_tgt, W_ih_dec + H_, b_ih_dec, p_tgd, VT_, G3H, E_, E_, H_ + E_, G3H);

    // ---- attention precompute: enc_ops @ W_attn[H:,:] + b_attn ----
    hmma_gemm<<<dim3(A_ / 128, (S_ * B_) / 128), 256, HM_SMEM>>>(
        p_ehi, p_elo, H_,
        p_Wat_h + H_, p_Wat_l + H_, 2 * H_, b_attn, p_encW, A_,
        nullptr, nullptr, 0, nullptr, nullptr, 0,
        NOSPLIT, H_);

    // ---- decoder: 4 launches per step ----
    for (int t = 1; t < T_; ++t) {
        // fused [hW | gh]: N = A + 3H = 4096, 128 CTAs, one wave
        hmma_gemm<<<dim3((A_ + G3H) / 128, B_ / 128), 256, HM_SMEM>>>(
            p_hhi, p_hlo, H_,
            p_Wat_h, p_Wat_l, 2 * H_, nullptr, p_hW, A_,
            p_Whd_h, p_Whd_l, H_, b_hh_dec, p_gates, G3H,
            A_, H_);
        attn_fused<<<B_, 256>>>(v_attn, out_attn, t);
        hmma_gemm<<<dim3(G3H / 128, B_ / 128), 256, HM_SMEM>>>(
            p_chi, p_clo, H_,
            p_Wid_h, p_Wid_l, H_, nullptr, p_gi, G3H,
            nullptr, nullptr, 0, nullptr, nullptr, 0,
            NOSPLIT, H_);
        dec_fused<<<B_, 288>>>(W_out, b_out, target, tf, t, out);
    }
}